// round 14
// baseline (speedup 1.0000x reference)
#include <cuda_runtime.h>
#include <math.h>
#include <stdint.h>

#define Bc   16
#define Hh   56
#define Wd   56
#define Cch  256
#define C4c  64
#define GKK  72
#define HWp  (Hh*Wd)      // 3136
#define Nn   (Bc*HWp)     // 50176
#define EPSv 1e-5f

// permuted channel slot (involution: 4x4 transpose within 16-channel groups)
#define P16(c) (((c) & ~15) | ((((c) & 3) << 2) | (((c) >> 2) & 3)))

// ---- scratch (device globals) ----
__device__ float g_t[(size_t)Nn*C4c];
__device__ float g_wk[(size_t)Nn*GKK];
__device__ float g_hw[(size_t)Nn*Cch];    // channel-PERMUTED
__device__ float g_cc[(size_t)Nn*Cch];    // channel-PERMUTED
__device__ float g_xr[(size_t)Nn*Cch];    // x rounded+permuted
__device__ float g_wmr[Cch*Cch];          // mlp_c_w rounded+k-permuted
__device__ float g_wpr[Cch*Cch];          // projcnn_w rounded+k-permuted
__device__ float g_w1r[C4c*Cch];          // conv1_w rounded+k-permuted
__device__ float g_sum[C4c];
__device__ float g_sumsq[C4c];
__device__ float g_asum[Bc*Cch];          // ORIGINAL channel order
__device__ float g_a0[Bc*Cch];            // channel-PERMUTED
__device__ float g_a1[Bc*Cch];            // channel-PERMUTED

// ================= helpers =================
__device__ __forceinline__ uint32_t f2tf(float f) {
    uint32_t r;
    asm("cvt.rna.tf32.f32 %0, %1;" : "=r"(r) : "f"(f));
    return r;
}
__device__ __forceinline__ float rtf(float f) { return __uint_as_float(f2tf(f)); }
__device__ __forceinline__ float4 tf4(float4 v) {
    v.x = rtf(v.x); v.y = rtf(v.y); v.z = rtf(v.z); v.w = rtf(v.w);
    return v;
}
__device__ __forceinline__ void mma_t(float* c, const uint32_t* a, uint32_t b0, uint32_t b1) {
    asm volatile(
        "mma.sync.aligned.m16n8k8.row.col.f32.tf32.tf32.f32 "
        "{%0,%1,%2,%3}, {%4,%5,%6,%7}, {%8,%9}, {%0,%1,%2,%3};"
        : "+f"(c[0]), "+f"(c[1]), "+f"(c[2]), "+f"(c[3])
        : "r"(a[0]), "r"(a[1]), "r"(a[2]), "r"(a[3]), "r"(b0), "r"(b1));
}
__device__ __forceinline__ uint32_t smem_u32(const void* p) {
    uint32_t a;
    asm("{ .reg .u64 t; cvta.to.shared.u64 t, %1; cvt.u32.u64 %0, t; }" : "=r"(a) : "l"(p));
    return a;
}
__device__ __forceinline__ void cp16(uint32_t dst, const void* src) {
    asm volatile("cp.async.cg.shared.global [%0], [%1], 16;" :: "r"(dst), "l"(src));
}
#define CP_COMMIT() asm volatile("cp.async.commit_group;")
#define CP_WAIT1()  asm volatile("cp.async.wait_group 1;")
#define CP_WAIT0()  asm volatile("cp.async.wait_group 0;")

#define SA 36            // legacy stride for kg kernel
#define ST 48            // permuted-layout row stride
#define STGF (256*ST)    // c2 stage: A 128 + B 128
#define DSMC (2*STGF*4)  // 98304
#define STG1 (192*ST)    // g1 stage: A 128 + B 64
#define DSG1 (2*STG1*4)  // 73728
#define STGO (384*ST)    // out3 stage: A 128 + B 256
#define DSMO (2*STGO*4)  // 147456

// ============================ kernels ============================

// ---------- prep: round+permute x (blocks 0..3135), weights + zero (3136..) ----------
__global__ __launch_bounds__(256) void k_prep(const float* __restrict__ x,
                                              const float* __restrict__ wm,
                                              const float* __restrict__ wp,
                                              const float* __restrict__ w1) {
    int tid = threadIdx.x;
    int bx = blockIdx.x;
    if (bx < 3136) {
        size_t idx = (size_t)bx * 256 + tid;
        size_t base = idx * 16;
        float4 v0 = *(const float4*)&x[base];
        float4 v1 = *(const float4*)&x[base + 4];
        float4 v2 = *(const float4*)&x[base + 8];
        float4 v3 = *(const float4*)&x[base + 12];
        *(float4*)&g_xr[base]      = tf4(make_float4(v0.x, v1.x, v2.x, v3.x));
        *(float4*)&g_xr[base + 4]  = tf4(make_float4(v0.y, v1.y, v2.y, v3.y));
        *(float4*)&g_xr[base + 8]  = tf4(make_float4(v0.z, v1.z, v2.z, v3.z));
        *(float4*)&g_xr[base + 12] = tf4(make_float4(v0.w, v1.w, v2.w, v3.w));
        return;
    }
    if (bx == 3136) {
        if (tid < C4c) { g_sum[tid] = 0.f; g_sumsq[tid] = 0.f; }
        for (int i = tid; i < Bc*Cch; i += 256) g_asum[i] = 0.f;
    }
    int idx = (bx - 3136) * 256 + tid;
    if (idx >= 9216) return;
    const float* src;  float* dst;  size_t base;
    if (idx < 4096)       { src = wm; dst = g_wmr; base = (size_t)idx * 16; }
    else if (idx < 8192)  { src = wp; dst = g_wpr; base = (size_t)(idx - 4096) * 16; }
    else                  { src = w1; dst = g_w1r; base = (size_t)(idx - 8192) * 16; }
    float4 v0 = *(const float4*)&src[base];
    float4 v1 = *(const float4*)&src[base + 4];
    float4 v2 = *(const float4*)&src[base + 8];
    float4 v3 = *(const float4*)&src[base + 12];
    *(float4*)&dst[base]      = tf4(make_float4(v0.x, v1.x, v2.x, v3.x));
    *(float4*)&dst[base + 4]  = tf4(make_float4(v0.y, v1.y, v2.y, v3.y));
    *(float4*)&dst[base + 8]  = tf4(make_float4(v0.z, v1.z, v2.z, v3.z));
    *(float4*)&dst[base + 12] = tf4(make_float4(v0.w, v1.w, v2.w, v3.w));
}

// ---------- GEMM1 (2-stage cp.async, 256 thr): t = xr @ w1r^T + b ; fused BN stats ----------
__global__ __launch_bounds__(256) void k_mma_g1c(const float* __restrict__ b1) {
    extern __shared__ float dsm[];
    __shared__ float scol[64], ssq[64];
    int tid = threadIdx.x, wid = tid >> 5, lane = tid & 31;
    int lr = lane >> 2, lc = lane & 3;
    int wm = wid & 3, wn = wid >> 2;    // 4 x 2 warps, warp tile 32 x 32
    int row0 = blockIdx.x * 128;
    if (tid < 64) { scol[tid] = 0.f; ssq[tid] = 0.f; }
    uint32_t sbase = smem_u32(dsm);

    auto stage_cp = [&](int ch, int s) {
        uint32_t sb0 = sbase + (uint32_t)(s * STG1 * 4);
        int k0 = ch * 32;
        #pragma unroll
        for (int i = 0; i < 4; i++) {
            int idx = tid + i*256, r = idx >> 3, q = idx & 7;
            cp16(sb0 + (uint32_t)((r*ST + q*4)*4),
                 &g_xr[(size_t)(row0 + r)*256 + k0 + q*4]);
        }
        #pragma unroll
        for (int i = 0; i < 2; i++) {
            int idx = tid + i*256, r = idx >> 3, q = idx & 7;
            cp16(sb0 + (uint32_t)((128*ST + r*ST + q*4)*4),
                 &g_w1r[(size_t)r*256 + k0 + q*4]);
        }
        CP_COMMIT();
    };
    stage_cp(0, 0);
    stage_cp(1, 1);

    float acc[2][4][4] = {};
    for (int ch = 0; ch < 8; ch++) {
        if (ch < 7) CP_WAIT1(); else CP_WAIT0();
        __syncthreads();
        const float* Ab = dsm + (ch & 1) * STG1;
        const float* Bb = Ab + 128*ST;
        #pragma unroll
        for (int g = 0; g < 2; g++) {
            float4 Alo[2], Ahi[2], Bv[4];
            #pragma unroll
            for (int mi = 0; mi < 2; mi++) {
                Alo[mi] = *(const float4*)&Ab[(wm*32 + mi*16 + lr)*ST + g*16 + lc*4];
                Ahi[mi] = *(const float4*)&Ab[(wm*32 + mi*16 + 8 + lr)*ST + g*16 + lc*4];
            }
            #pragma unroll
            for (int nj = 0; nj < 4; nj++)
                Bv[nj] = *(const float4*)&Bb[(wn*32 + nj*8 + lr)*ST + g*16 + lc*4];
            #pragma unroll
            for (int mi = 0; mi < 2; mi++) {
                uint32_t a0[4] = { __float_as_uint(Alo[mi].x), __float_as_uint(Ahi[mi].x),
                                   __float_as_uint(Alo[mi].y), __float_as_uint(Ahi[mi].y) };
                uint32_t a1[4] = { __float_as_uint(Alo[mi].z), __float_as_uint(Ahi[mi].z),
                                   __float_as_uint(Alo[mi].w), __float_as_uint(Ahi[mi].w) };
                #pragma unroll
                for (int nj = 0; nj < 4; nj++) {
                    mma_t(acc[mi][nj], a0, __float_as_uint(Bv[nj].x), __float_as_uint(Bv[nj].y));
                    mma_t(acc[mi][nj], a1, __float_as_uint(Bv[nj].z), __float_as_uint(Bv[nj].w));
                }
            }
        }
        __syncthreads();
        if (ch < 6) stage_cp(ch + 2, ch & 1);
    }

    #pragma unroll
    for (int nj = 0; nj < 4; nj++) {
        int c0 = wn*32 + nj*8 + lc*2;
        float bb0 = __ldg(&b1[c0]), bb1 = __ldg(&b1[c0+1]);
        float s0 = 0.f, s1 = 0.f, q0 = 0.f, q1 = 0.f;
        #pragma unroll
        for (int mi = 0; mi < 2; mi++) {
            int row = row0 + wm*32 + mi*16 + lr;
            float v0 = acc[mi][nj][0] + bb0;
            float v1 = acc[mi][nj][1] + bb1;
            float v2 = acc[mi][nj][2] + bb0;
            float v3 = acc[mi][nj][3] + bb1;
            *(float2*)&g_t[(size_t)row*64 + c0]     = make_float2(v0, v1);
            *(float2*)&g_t[(size_t)(row+8)*64 + c0] = make_float2(v2, v3);
            s0 += v0 + v2; s1 += v1 + v3;
            q0 += v0*v0 + v2*v2; q1 += v1*v1 + v3*v3;
        }
        atomicAdd(&scol[c0], s0);   atomicAdd(&scol[c0+1], s1);
        atomicAdd(&ssq[c0],  q0);   atomicAdd(&ssq[c0+1],  q1);
    }
    __syncthreads();
    if (tid < 64) {
        atomicAdd(&g_sum[tid],   scol[tid]);
        atomicAdd(&g_sumsq[tid], ssq[tid]);
    }
}

// ---------- kernel-gen (tf32 MMA, unchanged) ----------
__global__ __launch_bounds__(256) void k_mma_kg(const float* __restrict__ gamma,
                                                const float* __restrict__ beta,
                                                const float* __restrict__ w2,
                                                const float* __restrict__ b2) {
    __shared__ float As[128*SA];
    __shared__ float Bs[80*SA];
    __shared__ float sc[64], shf[64];
    int tid = threadIdx.x, wid = tid >> 5, lane = tid & 31;
    int lr = lane >> 2, lc = lane & 3;
    int wm = wid & 3, wn = wid >> 2;
    int row0 = blockIdx.x * 128;
    if (tid < 64) {
        const float invN = 1.0f / (float)Nn;
        float mu  = g_sum[tid] * invN;
        float var = g_sumsq[tid] * invN - mu * mu;
        float s = gamma[tid] * rsqrtf(var + EPSv);
        sc[tid]  = s;
        shf[tid] = beta[tid] - mu * s;
    }
    __syncthreads();

    float acc[2][5][4] = {};
    for (int ch = 0; ch < 2; ch++) {
        if (ch) __syncthreads();
        #pragma unroll
        for (int t = 0; t < 4; t++) {
            int idx = tid + t*256, r = idx >> 3, j = idx & 7;
            int c = ch*32 + j*4;
            float4 v = *(const float4*)&g_t[(size_t)(row0 + r)*64 + c];
            v.x = fmaxf(fmaf(v.x, sc[c+0], shf[c+0]), 0.f);
            v.y = fmaxf(fmaf(v.y, sc[c+1], shf[c+1]), 0.f);
            v.z = fmaxf(fmaf(v.z, sc[c+2], shf[c+2]), 0.f);
            v.w = fmaxf(fmaf(v.w, sc[c+3], shf[c+3]), 0.f);
            *(float4*)&As[r*SA + j*4] = tf4(v);
        }
        for (int idx = tid; idx < 80*8; idx += 256) {
            int r = idx >> 3, j = idx & 7;
            float4 v = make_float4(0.f, 0.f, 0.f, 0.f);
            if (r < 72) v = *(const float4*)&w2[(size_t)r*64 + ch*32 + j*4];
            *(float4*)&Bs[r*SA + j*4] = tf4(v);
        }
        __syncthreads();
        #pragma unroll
        for (int s = 0; s < 4; s++) {
            uint32_t a[2][4];
            #pragma unroll
            for (int mi = 0; mi < 2; mi++) {
                const float* Ap = &As[(wm*32 + mi*16 + lr)*SA + s*8 + lc];
                a[mi][0] = __float_as_uint(Ap[0]);
                a[mi][1] = __float_as_uint(Ap[8*SA]);
                a[mi][2] = __float_as_uint(Ap[4]);
                a[mi][3] = __float_as_uint(Ap[8*SA + 4]);
            }
            #pragma unroll
            for (int nj = 0; nj < 5; nj++) {
                const float* Bp = &Bs[(wn*40 + nj*8 + lr)*SA + s*8 + lc];
                uint32_t b0 = __float_as_uint(Bp[0]);
                uint32_t b1 = __float_as_uint(Bp[4]);
                mma_t(acc[0][nj], a[0], b0, b1);
                mma_t(acc[1][nj], a[1], b0, b1);
            }
        }
    }

    #pragma unroll
    for (int mi = 0; mi < 2; mi++) {
        int row = row0 + wm*32 + mi*16 + lr;
        #pragma unroll
        for (int nj = 0; nj < 5; nj++) {
            int col = wn*40 + nj*8 + lc*2;
            if (col < 72) {
                float bb0 = __ldg(&b2[col]), bb1 = __ldg(&b2[col+1]);
                *(float2*)&g_wk[(size_t)row*72 + col] =
                    make_float2(acc[mi][nj][0] + bb0, acc[mi][nj][1] + bb1);
                *(float2*)&g_wk[(size_t)(row+8)*72 + col] =
                    make_float2(acc[mi][nj][2] + bb0, acc[mi][nj][3] + bb1);
            }
        }
    }
}

// ---------- involution: channel-quad per thread (unchanged champion version) ----------
__global__ __launch_bounds__(256) void k_invo6(const float* __restrict__ x) {
    __shared__ float xs[4][58][32];
    __shared__ float ws[2][56][9];
    int bi = blockIdx.x;               // b*28 + hp/2
    int g  = blockIdx.y;
    int b = bi / 28, hp = (bi % 28) * 2;
    int tid = threadIdx.x;

    {
        int dy = tid >> 6, e = (tid >> 5) & 1, c = tid & 31;
        xs[dy][e ? 57 : 0][c] = 0.f;
    }
    for (int i = tid; i < 4*56*8; i += 256) {
        int c4 = i & 7, w = (i >> 3) % 56, dy = i / 448;
        int hh = hp + dy - 1;
        float4 v = make_float4(0.f, 0.f, 0.f, 0.f);
        if (hh >= 0 && hh < Hh)
            v = *(const float4*)&x[(((size_t)(b*Hh + hh))*Wd + w)*256 + g*32 + c4*4];
        *(float4*)&xs[dy][1 + w][c4*4] = v;
    }
    for (int i = tid; i < 2*56*9; i += 256) {
        int rr = i / (56*9), rem = i % (56*9), w = rem / 9, k = rem % 9;
        ws[rr][w][k] = g_wk[(((size_t)(b*Hh + hp + rr))*Wd + w)*72 + g*9 + k];
    }
    __syncthreads();

    int c4 = tid & 7, wq = tid >> 3;
    int slot = ((c4 & 4) << 2) | (c4 & 3);
    for (int w = wq; w < 56; w += 32) {
        float4 xv[4][3];
        #pragma unroll
        for (int dy = 0; dy < 4; dy++)
            #pragma unroll
            for (int dx = 0; dx < 3; dx++)
                xv[dy][dx] = *(const float4*)&xs[dy][w + dx][c4*4];
        #pragma unroll
        for (int rr = 0; rr < 2; rr++) {
            const float* wp9 = ws[rr][w];
            float4 a = make_float4(0.f, 0.f, 0.f, 0.f);
            #pragma unroll
            for (int dy = 0; dy < 3; dy++) {
                #pragma unroll
                for (int dx = 0; dx < 3; dx++) {
                    float wv = wp9[dy*3 + dx];
                    float4 xq = xv[rr + dy][dx];
                    a.x = fmaf(wv, xq.x, a.x);
                    a.y = fmaf(wv, xq.y, a.y);
                    a.z = fmaf(wv, xq.z, a.z);
                    a.w = fmaf(wv, xq.w, a.w);
                }
            }
            size_t ob = (((size_t)(b*Hh + hp + rr))*Wd + w)*256 + g*32 + slot;
            g_hw[ob + 0]  = a.x;
            g_hw[ob + 4]  = a.y;
            g_hw[ob + 8]  = a.z;
            g_hw[ob + 12] = a.w;
        }
    }
}

// ================= cp.async 64x64-warp-tile GEMM core (128 thr, A128 B128) =================
__device__ __forceinline__ void gemm_core(const float* __restrict__ Ag,
                                          const float* __restrict__ Bg,
                                          int row0, int col0,
                                          float acc[4][8][4],
                                          float* dsm, uint32_t sbase,
                                          int tid, int wm, int wn, int lr, int lc) {
    auto stage_cp = [&](int ch, int s) {
        uint32_t sb0 = sbase + (uint32_t)(s * STGF * 4);
        int k0 = ch * 32;
        #pragma unroll
        for (int i = 0; i < 8; i++) {
            int idx = tid + i*128, r = idx >> 3, q = idx & 7;
            cp16(sb0 + (uint32_t)((r*ST + q*4)*4),
                 &Ag[(size_t)(row0 + r)*256 + k0 + q*4]);
        }
        #pragma unroll
        for (int i = 0; i < 8; i++) {
            int idx = tid + i*128, r = idx >> 3, q = idx & 7;
            cp16(sb0 + (uint32_t)((128*ST + r*ST + q*4)*4),
                 &Bg[(size_t)(col0 + r)*256 + k0 + q*4]);
        }
        CP_COMMIT();
    };
    stage_cp(0, 0);
    stage_cp(1, 1);

    for (int ch = 0; ch < 8; ch++) {
        if (ch < 7) CP_WAIT1(); else CP_WAIT0();
        __syncthreads();
        const float* Ab = dsm + (ch & 1) * STGF;
        const float* Bb = Ab + 128*ST;
        #pragma unroll
        for (int g = 0; g < 2; g++) {
            float4 Alo[4], Ahi[4], Bv[8];
            #pragma unroll
            for (int mi = 0; mi < 4; mi++) {
                Alo[mi] = *(const float4*)&Ab[(wm*64 + mi*16 + lr)*ST + g*16 + lc*4];
                Ahi[mi] = *(const float4*)&Ab[(wm*64 + mi*16 + 8 + lr)*ST + g*16 + lc*4];
            }
            #pragma unroll
            for (int nj = 0; nj < 8; nj++)
                Bv[nj] = *(const float4*)&Bb[(wn*64 + nj*8 + lr)*ST + g*16 + lc*4];
            #pragma unroll
            for (int mi = 0; mi < 4; mi++) {
                uint32_t a0[4] = { __float_as_uint(Alo[mi].x), __float_as_uint(Ahi[mi].x),
                                   __float_as_uint(Alo[mi].y), __float_as_uint(Ahi[mi].y) };
                uint32_t a1[4] = { __float_as_uint(Alo[mi].z), __float_as_uint(Ahi[mi].z),
                                   __float_as_uint(Alo[mi].w), __float_as_uint(Ahi[mi].w) };
                #pragma unroll
                for (int nj = 0; nj < 8; nj++) {
                    mma_t(acc[mi][nj], a0, __float_as_uint(Bv[nj].x), __float_as_uint(Bv[nj].y));
                    mma_t(acc[mi][nj], a1, __float_as_uint(Bv[nj].z), __float_as_uint(Bv[nj].w));
                }
            }
        }
        __syncthreads();
        if (ch < 6) stage_cp(ch + 2, ch & 1);
    }
}

// ---------- GEMM c = xr @ wmr^T ; writes PERMUTED cc ; fused (hw+c) mean ----------
__global__ __launch_bounds__(128) void k_mma_c2() {
    extern __shared__ float dsm[];
    __shared__ float scol[2][128];
    int tid = threadIdx.x, wid = tid >> 5, lane = tid & 31;
    int lr = lane >> 2, lc = lane & 3;
    int wm = wid >> 1, wn = wid & 1;
    int row0 = blockIdx.x * 128, col0 = blockIdx.y * 128;
    scol[0][tid] = 0.f; scol[1][tid] = 0.f;
    uint32_t sbase = smem_u32(dsm);

    float acc[4][8][4] = {};
    gemm_core(g_xr, g_wmr, row0, col0, acc, dsm, sbase, tid, wm, wn, lr, lc);

    int bimg = row0 / HWp;
    int bsplit = (bimg + 1) * HWp;
    #pragma unroll
    for (int nj = 0; nj < 8; nj++) {
        int colr = wn*64 + nj*8 + lc*2;
        int col = col0 + colr;
        int p0 = P16(col), p1 = P16(col + 1);
        float s0[2] = {0.f, 0.f}, s1[2] = {0.f, 0.f};
        #pragma unroll
        for (int mi = 0; mi < 4; mi++) {
            int row = row0 + wm*64 + mi*16 + lr;
            size_t ra = (size_t)row*256, rb = (size_t)(row+8)*256;
            float c0x = acc[mi][nj][0], c0y = acc[mi][nj][1];
            float c1x = acc[mi][nj][2], c1y = acc[mi][nj][3];
            g_cc[ra + p0] = c0x;  g_cc[ra + p1] = c0y;
            g_cc[rb + p0] = c1x;  g_cc[rb + p1] = c1y;
            float h0x = g_hw[ra + p0], h0y = g_hw[ra + p1];
            float h1x = g_hw[rb + p0], h1y = g_hw[rb + p1];
            int r0 = (row >= bsplit) ? 1 : 0;
            int r1 = (row + 8 >= bsplit) ? 1 : 0;
            s0[r0] += c0x + h0x;  s1[r0] += c0y + h0y;
            s0[r1] += c1x + h1x;  s1[r1] += c1y + h1y;
        }
        atomicAdd(&scol[0][colr],   s0[0]);
        atomicAdd(&scol[0][colr+1], s1[0]);
        if (s0[1] != 0.f || s1[1] != 0.f) {
            atomicAdd(&scol[1][colr],   s0[1]);
            atomicAdd(&scol[1][colr+1], s1[1]);
        }
    }
    __syncthreads();
    atomicAdd(&g_asum[bimg*256 + col0 + tid], scol[0][tid]);
    float v1 = scol[1][tid];
    if (v1 != 0.f && bimg + 1 < Bc)
        atomicAdd(&g_asum[(bimg+1)*256 + col0 + tid], v1);
}

// ---------- reweight MLP + pairwise softmax; a0/a1 stored PERMUTED ----------
__global__ __launch_bounds__(256) void k_small2(const float* __restrict__ fc1w,
                                                const float* __restrict__ fc1b,
                                                const float* __restrict__ fc2w,
                                                const float* __restrict__ fc2b) {
    __shared__ float sm[256];
    __shared__ float h1[64];
    int b = blockIdx.x, tid = threadIdx.x;
    sm[tid] = g_asum[b*256 + tid] * (1.0f / (float)HWp);
    __syncthreads();
    int o = tid >> 2, qtr = tid & 3;
    {
        const float* w = &fc1w[(size_t)o*256 + qtr*64];
        const float* s = &sm[qtr*64];
        float p = 0.f;
        #pragma unroll 8
        for (int c = 0; c < 64; c++) p += s[c] * w[c];
        p += __shfl_xor_sync(0xffffffffu, p, 1);
        p += __shfl_xor_sync(0xffffffffu, p, 2);
        if (qtr == 0) {
            float a = p + fc1b[o];
            h1[o] = 0.5f * a * (1.0f + erff(a * 0.70710678118654752f));
        }
    }
    __syncthreads();
    int c = tid;
    float l0 = fc2b[2*c], l1 = fc2b[2*c+1];
    #pragma unroll 8
    for (int k = 0; k < 64; k++) {
        float hv = h1[k];
        l0 += hv * fc2w[(size_t)(2*c)*64 + k];
        l1 += hv * fc2w[(size_t)(2*c+1)*64 + k];
    }
    float m = fmaxf(l0, l1);
    float e0 = expf(l0 - m), e1 = expf(l1 - m);
    float s = 1.f / (e0 + e1);
    int pc = P16(c);
    g_a0[b*256 + pc] = e0 * s;
    g_a1[b*256 + pc] = e1 * s;
}

// ---------- final GEMM (full-width 128x256, fused y-assembly) ----------
__global__ __launch_bounds__(256) void k_mma_out3(const float* __restrict__ bp,
                                                  float* __restrict__ out) {
    extern __shared__ float dsm[];
    __shared__ float sa0[512], sa1[512];
    int tid = threadIdx.x, wid = tid >> 5, lane = tid & 31;
    int lr = lane >> 2, lc = lane & 3;
    int wm = wid >> 2, wn = wid & 3;
    int row0 = blockIdx.x * 128;
    int bimg = row0 / HWp;
    int bimg2 = (bimg + 1 < Bc) ? bimg + 1 : bimg;
    int bsplit = (bimg + 1) * HWp;
    sa0[tid]       = g_a0[bimg*256 + tid];
    sa1[tid]       = g_a1[bimg*256 + tid];
    sa0[256 + tid] = g_a0[bimg2*256 + tid];
    sa1[256 + tid] = g_a1[bimg2*256 + tid];
    uint32_t sbase = smem_u32(dsm);

    auto cpB = [&](int ch, int s) {
        uint32_t sb0 = sbase + (uint32_t)(s * STGO * 4);
        int k0 = ch * 32;
        #pragma unroll
        for (int i = 0; i < 8; i++) {
            int idx = tid + i*256, r = idx >> 3, q = idx & 7;
            cp16(sb0 + (uint32_t)((128*ST + r*ST + q*4)*4),
                 &g_wpr[(size_t)r*256 + k0 + q*4]);
        }
        CP_COMMIT();
    };
    float4 fh[4], fc[4];
    auto ldA = [&](int ch) {
        int k0 = ch * 32;
        #pragma unroll
        for (int i = 0; i < 4; i++) {
            int idx = tid + i*256, r = idx >> 3, q = idx & 7;
            size_t base = (size_t)(row0 + r)*256 + k0 + q*4;
            fh[i] = *(const float4*)&g_hw[base];
            fc[i] = *(const float4*)&g_cc[base];
        }
    };
    auto stA = [&](int ch, int s) {
        int k0 = ch * 32;
        #pragma unroll
        for (int i = 0; i < 4; i++) {
            int idx = tid + i*256, r = idx >> 3, q = idx & 7;
            int rel = ((row0 + r) >= bsplit) ? 256 : 0;
            int ki = rel + k0 + q*4;
            float4 v;
            v.x = rtf(fh[i].x * sa0[ki+0] + fc[i].x * sa1[ki+0]);
            v.y = rtf(fh[i].y * sa0[ki+1] + fc[i].y * sa1[ki+1]);
            v.z = rtf(fh[i].z * sa0[ki+2] + fc[i].z * sa1[ki+2]);
            v.w = rtf(fh[i].w * sa0[ki+3] + fc[i].w * sa1[ki+3]);
            *(float4*)&dsm[s*STGO + r*ST + q*4] = v;
        }
    };

    cpB(0, 0);
    cpB(1, 1);
    ldA(0);
    __syncthreads();
    stA(0, 0);
    ldA(1);

    float acc[4][8][4] = {};
    for (int ch = 0; ch < 8; ch++) {
        if (ch < 7) CP_WAIT1(); else CP_WAIT0();
        __syncthreads();
        const float* Ab = dsm + (ch & 1) * STGO;
        const float* Bb = Ab + 128*ST;
        #pragma unroll
        for (int g = 0; g < 2; g++) {
            float4 Alo[4], Ahi[4], Bv[8];
            #pragma unroll
            for (int mi = 0; mi < 4; mi++) {
                Alo[mi] = *(const float4*)&Ab[(wm*64 + mi*16 + lr)*ST + g*16 + lc*4];
                Ahi[mi] = *(const float4*)&Ab[(wm*64 + mi*16 + 8 + lr)*ST + g*16 + lc*4];
            }
            #pragma unroll
            for (int nj = 0; nj < 8; nj++)
                Bv[nj] = *(const float4*)&Bb[(wn*64 + nj*8 + lr)*ST + g*16 + lc*4];
            #pragma unroll
            for (int mi = 0; mi < 4; mi++) {
                uint32_t a0[4] = { __float_as_uint(Alo[mi].x), __float_as_uint(Ahi[mi].x),
                                   __float_as_uint(Alo[mi].y), __float_as_uint(Ahi[mi].y) };
                uint32_t a1[4] = { __float_as_uint(Alo[mi].z), __float_as_uint(Ahi[mi].z),
                                   __float_as_uint(Alo[mi].w), __float_as_uint(Ahi[mi].w) };
                #pragma unroll
                for (int nj = 0; nj < 8; nj++) {
                    mma_t(acc[mi][nj], a0, __float_as_uint(Bv[nj].x), __float_as_uint(Bv[nj].y));
                    mma_t(acc[mi][nj], a1, __float_as_uint(Bv[nj].z), __float_as_uint(Bv[nj].w));
                }
            }
            if (g == 0 && ch < 7) stA(ch + 1, (ch + 1) & 1);
        }
        if (ch < 6) ldA(ch + 2);
        __syncthreads();
        if (ch < 6) cpB(ch + 2, ch & 1);
    }

    #pragma unroll
    for (int nj = 0; nj < 8; nj++) {
        int col = wn*64 + nj*8 + lc*2;
        float bb0 = __ldg(&bp[col]), bb1 = __ldg(&bp[col+1]);
        #pragma unroll
        for (int mi = 0; mi < 4; mi++) {
            int row = row0 + wm*64 + mi*16 + lr;
            *(float2*)&out[(size_t)row*256 + col] =
                make_float2(acc[mi][nj][0] + bb0, acc[mi][nj][1] + bb1);
            *(float2*)&out[(size_t)(row+8)*256 + col] =
                make_float2(acc[mi][nj][2] + bb0, acc[mi][nj][3] + bb1);
        }
    }
}

extern "C" void kernel_launch(void* const* d_in, const int* in_sizes, int n_in,
                              void* d_out, int out_size) {
    const float* x        = (const float*)d_in[0];
    const float* conv1_w  = (const float*)d_in[1];
    const float* conv1_b  = (const float*)d_in[2];
    const float* bn_gamma = (const float*)d_in[3];
    const float* bn_beta  = (const float*)d_in[4];
    const float* conv2_w  = (const float*)d_in[5];
    const float* conv2_b  = (const float*)d_in[6];
    const float* mlp_c_w  = (const float*)d_in[7];
    const float* fc1_w    = (const float*)d_in[8];
    const float* fc1_b    = (const float*)d_in[9];
    const float* fc2_w    = (const float*)d_in[10];
    const float* fc2_b    = (const float*)d_in[11];
    const float* projcnn_w= (const float*)d_in[12];
    const float* projcnn_b= (const float*)d_in[13];
    float* out = (float*)d_out;

    cudaFuncSetAttribute(k_mma_c2,   cudaFuncAttributeMaxDynamicSharedMemorySize, DSMC);
    cudaFuncSetAttribute(k_mma_out3, cudaFuncAttributeMaxDynamicSharedMemorySize, DSMO);
    cudaFuncSetAttribute(k_mma_g1c,  cudaFuncAttributeMaxDynamicSharedMemorySize, DSG1);

    k_prep   <<<3136 + 36, 256>>>(x, mlp_c_w, projcnn_w, conv1_w);
    k_mma_g1c<<<Nn/128, 256, DSG1>>>(conv1_b);
    k_mma_kg <<<Nn/128, 256>>>(bn_gamma, bn_beta, conv2_w, conv2_b);
    k_invo6  <<<dim3(Bc*28, 8), 256>>>(x);
    k_mma_c2 <<<dim3(Nn/128, 2), 128, DSMC>>>();
    k_small2 <<<Bc, 256>>>(fc1_w, fc1_b, fc2_w, fc2_b);
    k_mma_out3<<<Nn/128, 256, DSMO>>>(projcnn_b, out);
}

// round 15
// speedup vs baseline: 1.0448x; 1.0448x over previous
#include <cuda_runtime.h>
#include <math.h>
#include <stdint.h>

#define Bc   16
#define Hh   56
#define Wd   56
#define Cch  256
#define C4c  64
#define GKK  72
#define HWp  (Hh*Wd)      // 3136
#define Nn   (Bc*HWp)     // 50176
#define EPSv 1e-5f

// permuted channel slot (involution: 4x4 transpose within 16-channel groups)
#define P16(c) (((c) & ~15) | ((((c) & 3) << 2) | (((c) >> 2) & 3)))

// ---- scratch (device globals) ----
__device__ float g_t[(size_t)Nn*C4c];
__device__ float g_wk[(size_t)Nn*GKK];
__device__ float g_hw[(size_t)Nn*Cch];    // channel-PERMUTED
__device__ float g_cc[(size_t)Nn*Cch];    // channel-PERMUTED
__device__ float g_xr[(size_t)Nn*Cch];    // x rounded+permuted
__device__ float g_wmr[Cch*Cch];          // mlp_c_w rounded+k-permuted
__device__ float g_wpr[Cch*Cch];          // projcnn_w rounded+k-permuted
__device__ float g_w1r[C4c*Cch];          // conv1_w rounded+k-permuted
__device__ float g_sum[C4c];
__device__ float g_sumsq[C4c];
__device__ float g_asum[Bc*Cch];          // ORIGINAL channel order
__device__ float g_a0[Bc*Cch];            // channel-PERMUTED
__device__ float g_a1[Bc*Cch];            // channel-PERMUTED

// ================= helpers =================
__device__ __forceinline__ uint32_t f2tf(float f) {
    uint32_t r;
    asm("cvt.rna.tf32.f32 %0, %1;" : "=r"(r) : "f"(f));
    return r;
}
__device__ __forceinline__ float rtf(float f) { return __uint_as_float(f2tf(f)); }
__device__ __forceinline__ float4 tf4(float4 v) {
    v.x = rtf(v.x); v.y = rtf(v.y); v.z = rtf(v.z); v.w = rtf(v.w);
    return v;
}
__device__ __forceinline__ void mma_t(float* c, const uint32_t* a, uint32_t b0, uint32_t b1) {
    asm volatile(
        "mma.sync.aligned.m16n8k8.row.col.f32.tf32.tf32.f32 "
        "{%0,%1,%2,%3}, {%4,%5,%6,%7}, {%8,%9}, {%0,%1,%2,%3};"
        : "+f"(c[0]), "+f"(c[1]), "+f"(c[2]), "+f"(c[3])
        : "r"(a[0]), "r"(a[1]), "r"(a[2]), "r"(a[3]), "r"(b0), "r"(b1));
}
__device__ __forceinline__ uint32_t smem_u32(const void* p) {
    uint32_t a;
    asm("{ .reg .u64 t; cvta.to.shared.u64 t, %1; cvt.u32.u64 %0, t; }" : "=r"(a) : "l"(p));
    return a;
}
__device__ __forceinline__ void cp16(uint32_t dst, const void* src) {
    asm volatile("cp.async.cg.shared.global [%0], [%1], 16;" :: "r"(dst), "l"(src));
}
#define CP_COMMIT() asm volatile("cp.async.commit_group;")
#define CP_WAIT1()  asm volatile("cp.async.wait_group 1;")
#define CP_WAIT0()  asm volatile("cp.async.wait_group 0;")

#define SA 36            // legacy stride for kg kernel
#define ST 48            // permuted-layout row stride
#define STGF (256*ST)    // c2 stage: A 128 + B 128
#define DSMC (2*STGF*4)  // 98304
#define STG1 (192*ST)    // g1 stage: A 128 + B 64
#define DSG1 (2*STG1*4)  // 73728  (2-stage, 128 thr -> 3 CTAs/SM)
#define STGO (384*ST)    // out3 stage: A 128 + B 256
#define DSMO (2*STGO*4)  // 147456

// ============================ kernels ============================

// ---------- prep: round+permute x (blocks 0..3135), weights + zero (3136..) ----------
__global__ __launch_bounds__(256) void k_prep(const float* __restrict__ x,
                                              const float* __restrict__ wm,
                                              const float* __restrict__ wp,
                                              const float* __restrict__ w1) {
    int tid = threadIdx.x;
    int bx = blockIdx.x;
    if (bx < 3136) {
        size_t idx = (size_t)bx * 256 + tid;
        size_t base = idx * 16;
        float4 v0 = *(const float4*)&x[base];
        float4 v1 = *(const float4*)&x[base + 4];
        float4 v2 = *(const float4*)&x[base + 8];
        float4 v3 = *(const float4*)&x[base + 12];
        *(float4*)&g_xr[base]      = tf4(make_float4(v0.x, v1.x, v2.x, v3.x));
        *(float4*)&g_xr[base + 4]  = tf4(make_float4(v0.y, v1.y, v2.y, v3.y));
        *(float4*)&g_xr[base + 8]  = tf4(make_float4(v0.z, v1.z, v2.z, v3.z));
        *(float4*)&g_xr[base + 12] = tf4(make_float4(v0.w, v1.w, v2.w, v3.w));
        return;
    }
    if (bx == 3136) {
        if (tid < C4c) { g_sum[tid] = 0.f; g_sumsq[tid] = 0.f; }
        for (int i = tid; i < Bc*Cch; i += 256) g_asum[i] = 0.f;
    }
    int idx = (bx - 3136) * 256 + tid;
    if (idx >= 9216) return;
    const float* src;  float* dst;  size_t base;
    if (idx < 4096)       { src = wm; dst = g_wmr; base = (size_t)idx * 16; }
    else if (idx < 8192)  { src = wp; dst = g_wpr; base = (size_t)(idx - 4096) * 16; }
    else                  { src = w1; dst = g_w1r; base = (size_t)(idx - 8192) * 16; }
    float4 v0 = *(const float4*)&src[base];
    float4 v1 = *(const float4*)&src[base + 4];
    float4 v2 = *(const float4*)&src[base + 8];
    float4 v3 = *(const float4*)&src[base + 12];
    *(float4*)&dst[base]      = tf4(make_float4(v0.x, v1.x, v2.x, v3.x));
    *(float4*)&dst[base + 4]  = tf4(make_float4(v0.y, v1.y, v2.y, v3.y));
    *(float4*)&dst[base + 8]  = tf4(make_float4(v0.z, v1.z, v2.z, v3.z));
    *(float4*)&dst[base + 12] = tf4(make_float4(v0.w, v1.w, v2.w, v3.w));
}

// ---------- GEMM1 (2-stage cp.async, 128 thr): t = xr @ w1r^T + b ; fused BN stats ----------
__global__ __launch_bounds__(128) void k_mma_g1b(const float* __restrict__ b1) {
    extern __shared__ float dsm[];
    __shared__ float scol[64], ssq[64];
    int tid = threadIdx.x, wid = tid >> 5, lane = tid & 31;
    int lr = lane >> 2, lc = lane & 3;
    int wm = wid & 1, wn = wid >> 1;    // warp tile 64 x 32
    int row0 = blockIdx.x * 128;
    if (tid < 64) { scol[tid] = 0.f; ssq[tid] = 0.f; }
    uint32_t sbase = smem_u32(dsm);

    auto stage_cp = [&](int ch, int s) {
        uint32_t sb0 = sbase + (uint32_t)(s * STG1 * 4);
        int k0 = ch * 32;
        #pragma unroll
        for (int i = 0; i < 8; i++) {
            int idx = tid + i*128, r = idx >> 3, q = idx & 7;
            cp16(sb0 + (uint32_t)((r*ST + q*4)*4),
                 &g_xr[(size_t)(row0 + r)*256 + k0 + q*4]);
        }
        #pragma unroll
        for (int i = 0; i < 4; i++) {
            int idx = tid + i*128, r = idx >> 3, q = idx & 7;
            cp16(sb0 + (uint32_t)((128*ST + r*ST + q*4)*4),
                 &g_w1r[(size_t)r*256 + k0 + q*4]);
        }
        CP_COMMIT();
    };
    stage_cp(0, 0);
    stage_cp(1, 1);

    float acc[4][4][4] = {};
    for (int ch = 0; ch < 8; ch++) {
        if (ch < 7) CP_WAIT1(); else CP_WAIT0();
        __syncthreads();
        const float* Ab = dsm + (ch & 1) * STG1;
        const float* Bb = Ab + 128*ST;
        #pragma unroll
        for (int g = 0; g < 2; g++) {
            float4 Alo[4], Ahi[4], Bv[4];
            #pragma unroll
            for (int mi = 0; mi < 4; mi++) {
                Alo[mi] = *(const float4*)&Ab[(wm*64 + mi*16 + lr)*ST + g*16 + lc*4];
                Ahi[mi] = *(const float4*)&Ab[(wm*64 + mi*16 + 8 + lr)*ST + g*16 + lc*4];
            }
            #pragma unroll
            for (int nj = 0; nj < 4; nj++)
                Bv[nj] = *(const float4*)&Bb[(wn*32 + nj*8 + lr)*ST + g*16 + lc*4];
            #pragma unroll
            for (int mi = 0; mi < 4; mi++) {
                uint32_t a0[4] = { __float_as_uint(Alo[mi].x), __float_as_uint(Ahi[mi].x),
                                   __float_as_uint(Alo[mi].y), __float_as_uint(Ahi[mi].y) };
                uint32_t a1[4] = { __float_as_uint(Alo[mi].z), __float_as_uint(Ahi[mi].z),
                                   __float_as_uint(Alo[mi].w), __float_as_uint(Ahi[mi].w) };
                #pragma unroll
                for (int nj = 0; nj < 4; nj++) {
                    mma_t(acc[mi][nj], a0, __float_as_uint(Bv[nj].x), __float_as_uint(Bv[nj].y));
                    mma_t(acc[mi][nj], a1, __float_as_uint(Bv[nj].z), __float_as_uint(Bv[nj].w));
                }
            }
        }
        __syncthreads();
        if (ch < 6) stage_cp(ch + 2, ch & 1);
    }

    #pragma unroll
    for (int nj = 0; nj < 4; nj++) {
        int c0 = wn*32 + nj*8 + lc*2;
        float bb0 = __ldg(&b1[c0]), bb1 = __ldg(&b1[c0+1]);
        float s0 = 0.f, s1 = 0.f, q0 = 0.f, q1 = 0.f;
        #pragma unroll
        for (int mi = 0; mi < 4; mi++) {
            int row = row0 + wm*64 + mi*16 + lr;
            float v0 = acc[mi][nj][0] + bb0;
            float v1 = acc[mi][nj][1] + bb1;
            float v2 = acc[mi][nj][2] + bb0;
            float v3 = acc[mi][nj][3] + bb1;
            *(float2*)&g_t[(size_t)row*64 + c0]     = make_float2(v0, v1);
            *(float2*)&g_t[(size_t)(row+8)*64 + c0] = make_float2(v2, v3);
            s0 += v0 + v2; s1 += v1 + v3;
            q0 += v0*v0 + v2*v2; q1 += v1*v1 + v3*v3;
        }
        atomicAdd(&scol[c0], s0);   atomicAdd(&scol[c0+1], s1);
        atomicAdd(&ssq[c0],  q0);   atomicAdd(&ssq[c0+1],  q1);
    }
    __syncthreads();
    if (tid < 64) {
        atomicAdd(&g_sum[tid],   scol[tid]);
        atomicAdd(&g_sumsq[tid], ssq[tid]);
    }
}

// ---------- kernel-gen (tf32 MMA) ----------
__global__ __launch_bounds__(256) void k_mma_kg(const float* __restrict__ gamma,
                                                const float* __restrict__ beta,
                                                const float* __restrict__ w2,
                                                const float* __restrict__ b2) {
    __shared__ float As[128*SA];
    __shared__ float Bs[80*SA];
    __shared__ float sc[64], shf[64];
    int tid = threadIdx.x, wid = tid >> 5, lane = tid & 31;
    int lr = lane >> 2, lc = lane & 3;
    int wm = wid & 3, wn = wid >> 2;
    int row0 = blockIdx.x * 128;
    if (tid < 64) {
        const float invN = 1.0f / (float)Nn;
        float mu  = g_sum[tid] * invN;
        float var = g_sumsq[tid] * invN - mu * mu;
        float s = gamma[tid] * rsqrtf(var + EPSv);
        sc[tid]  = s;
        shf[tid] = beta[tid] - mu * s;
    }
    __syncthreads();

    float acc[2][5][4] = {};
    for (int ch = 0; ch < 2; ch++) {
        if (ch) __syncthreads();
        #pragma unroll
        for (int t = 0; t < 4; t++) {
            int idx = tid + t*256, r = idx >> 3, j = idx & 7;
            int c = ch*32 + j*4;
            float4 v = *(const float4*)&g_t[(size_t)(row0 + r)*64 + c];
            v.x = fmaxf(fmaf(v.x, sc[c+0], shf[c+0]), 0.f);
            v.y = fmaxf(fmaf(v.y, sc[c+1], shf[c+1]), 0.f);
            v.z = fmaxf(fmaf(v.z, sc[c+2], shf[c+2]), 0.f);
            v.w = fmaxf(fmaf(v.w, sc[c+3], shf[c+3]), 0.f);
            *(float4*)&As[r*SA + j*4] = tf4(v);
        }
        for (int idx = tid; idx < 80*8; idx += 256) {
            int r = idx >> 3, j = idx & 7;
            float4 v = make_float4(0.f, 0.f, 0.f, 0.f);
            if (r < 72) v = *(const float4*)&w2[(size_t)r*64 + ch*32 + j*4];
            *(float4*)&Bs[r*SA + j*4] = tf4(v);
        }
        __syncthreads();
        #pragma unroll
        for (int s = 0; s < 4; s++) {
            uint32_t a[2][4];
            #pragma unroll
            for (int mi = 0; mi < 2; mi++) {
                const float* Ap = &As[(wm*32 + mi*16 + lr)*SA + s*8 + lc];
                a[mi][0] = __float_as_uint(Ap[0]);
                a[mi][1] = __float_as_uint(Ap[8*SA]);
                a[mi][2] = __float_as_uint(Ap[4]);
                a[mi][3] = __float_as_uint(Ap[8*SA + 4]);
            }
            #pragma unroll
            for (int nj = 0; nj < 5; nj++) {
                const float* Bp = &Bs[(wn*40 + nj*8 + lr)*SA + s*8 + lc];
                uint32_t b0 = __float_as_uint(Bp[0]);
                uint32_t b1 = __float_as_uint(Bp[4]);
                mma_t(acc[0][nj], a[0], b0, b1);
                mma_t(acc[1][nj], a[1], b0, b1);
            }
        }
    }

    #pragma unroll
    for (int mi = 0; mi < 2; mi++) {
        int row = row0 + wm*32 + mi*16 + lr;
        #pragma unroll
        for (int nj = 0; nj < 5; nj++) {
            int col = wn*40 + nj*8 + lc*2;
            if (col < 72) {
                float bb0 = __ldg(&b2[col]), bb1 = __ldg(&b2[col+1]);
                *(float2*)&g_wk[(size_t)row*72 + col] =
                    make_float2(acc[mi][nj][0] + bb0, acc[mi][nj][1] + bb1);
                *(float2*)&g_wk[(size_t)(row+8)*72 + col] =
                    make_float2(acc[mi][nj][2] + bb0, acc[mi][nj][3] + bb1);
            }
        }
    }
}

// ---------- involution: channel-quad per thread (champion version) ----------
__global__ __launch_bounds__(256) void k_invo6(const float* __restrict__ x) {
    __shared__ float xs[4][58][32];
    __shared__ float ws[2][56][9];
    int bi = blockIdx.x;               // b*28 + hp/2
    int g  = blockIdx.y;
    int b = bi / 28, hp = (bi % 28) * 2;
    int tid = threadIdx.x;

    {
        int dy = tid >> 6, e = (tid >> 5) & 1, c = tid & 31;
        xs[dy][e ? 57 : 0][c] = 0.f;
    }
    for (int i = tid; i < 4*56*8; i += 256) {
        int c4 = i & 7, w = (i >> 3) % 56, dy = i / 448;
        int hh = hp + dy - 1;
        float4 v = make_float4(0.f, 0.f, 0.f, 0.f);
        if (hh >= 0 && hh < Hh)
            v = *(const float4*)&x[(((size_t)(b*Hh + hh))*Wd + w)*256 + g*32 + c4*4];
        *(float4*)&xs[dy][1 + w][c4*4] = v;
    }
    for (int i = tid; i < 2*56*9; i += 256) {
        int rr = i / (56*9), rem = i % (56*9), w = rem / 9, k = rem % 9;
        ws[rr][w][k] = g_wk[(((size_t)(b*Hh + hp + rr))*Wd + w)*72 + g*9 + k];
    }
    __syncthreads();

    int c4 = tid & 7, wq = tid >> 3;
    int slot = ((c4 & 4) << 2) | (c4 & 3);
    for (int w = wq; w < 56; w += 32) {
        float4 xv[4][3];
        #pragma unroll
        for (int dy = 0; dy < 4; dy++)
            #pragma unroll
            for (int dx = 0; dx < 3; dx++)
                xv[dy][dx] = *(const float4*)&xs[dy][w + dx][c4*4];
        #pragma unroll
        for (int rr = 0; rr < 2; rr++) {
            const float* wp9 = ws[rr][w];
            float4 a = make_float4(0.f, 0.f, 0.f, 0.f);
            #pragma unroll
            for (int dy = 0; dy < 3; dy++) {
                #pragma unroll
                for (int dx = 0; dx < 3; dx++) {
                    float wv = wp9[dy*3 + dx];
                    float4 xq = xv[rr + dy][dx];
                    a.x = fmaf(wv, xq.x, a.x);
                    a.y = fmaf(wv, xq.y, a.y);
                    a.z = fmaf(wv, xq.z, a.z);
                    a.w = fmaf(wv, xq.w, a.w);
                }
            }
            size_t ob = (((size_t)(b*Hh + hp + rr))*Wd + w)*256 + g*32 + slot;
            g_hw[ob + 0]  = a.x;
            g_hw[ob + 4]  = a.y;
            g_hw[ob + 8]  = a.z;
            g_hw[ob + 12] = a.w;
        }
    }
}

// ================= cp.async 64x64-warp-tile GEMM core (128 thr, A128 B128) =================
__device__ __forceinline__ void gemm_core(const float* __restrict__ Ag,
                                          const float* __restrict__ Bg,
                                          int row0, int col0,
                                          float acc[4][8][4],
                                          float* dsm, uint32_t sbase,
                                          int tid, int wm, int wn, int lr, int lc) {
    auto stage_cp = [&](int ch, int s) {
        uint32_t sb0 = sbase + (uint32_t)(s * STGF * 4);
        int k0 = ch * 32;
        #pragma unroll
        for (int i = 0; i < 8; i++) {
            int idx = tid + i*128, r = idx >> 3, q = idx & 7;
            cp16(sb0 + (uint32_t)((r*ST + q*4)*4),
                 &Ag[(size_t)(row0 + r)*256 + k0 + q*4]);
        }
        #pragma unroll
        for (int i = 0; i < 8; i++) {
            int idx = tid + i*128, r = idx >> 3, q = idx & 7;
            cp16(sb0 + (uint32_t)((128*ST + r*ST + q*4)*4),
                 &Bg[(size_t)(col0 + r)*256 + k0 + q*4]);
        }
        CP_COMMIT();
    };
    stage_cp(0, 0);
    stage_cp(1, 1);

    for (int ch = 0; ch < 8; ch++) {
        if (ch < 7) CP_WAIT1(); else CP_WAIT0();
        __syncthreads();
        const float* Ab = dsm + (ch & 1) * STGF;
        const float* Bb = Ab + 128*ST;
        #pragma unroll
        for (int g = 0; g < 2; g++) {
            float4 Alo[4], Ahi[4], Bv[8];
            #pragma unroll
            for (int mi = 0; mi < 4; mi++) {
                Alo[mi] = *(const float4*)&Ab[(wm*64 + mi*16 + lr)*ST + g*16 + lc*4];
                Ahi[mi] = *(const float4*)&Ab[(wm*64 + mi*16 + 8 + lr)*ST + g*16 + lc*4];
            }
            #pragma unroll
            for (int nj = 0; nj < 8; nj++)
                Bv[nj] = *(const float4*)&Bb[(wn*64 + nj*8 + lr)*ST + g*16 + lc*4];
            #pragma unroll
            for (int mi = 0; mi < 4; mi++) {
                uint32_t a0[4] = { __float_as_uint(Alo[mi].x), __float_as_uint(Ahi[mi].x),
                                   __float_as_uint(Alo[mi].y), __float_as_uint(Ahi[mi].y) };
                uint32_t a1[4] = { __float_as_uint(Alo[mi].z), __float_as_uint(Ahi[mi].z),
                                   __float_as_uint(Alo[mi].w), __float_as_uint(Ahi[mi].w) };
                #pragma unroll
                for (int nj = 0; nj < 8; nj++) {
                    mma_t(acc[mi][nj], a0, __float_as_uint(Bv[nj].x), __float_as_uint(Bv[nj].y));
                    mma_t(acc[mi][nj], a1, __float_as_uint(Bv[nj].z), __float_as_uint(Bv[nj].w));
                }
            }
        }
        __syncthreads();
        if (ch < 6) stage_cp(ch + 2, ch & 1);
    }
}

// ---------- GEMM c = xr @ wmr^T ; writes PERMUTED cc ; fused (hw+c) mean ----------
__global__ __launch_bounds__(128) void k_mma_c2() {
    extern __shared__ float dsm[];
    __shared__ float scol[2][128];
    int tid = threadIdx.x, wid = tid >> 5, lane = tid & 31;
    int lr = lane >> 2, lc = lane & 3;
    int wm = wid >> 1, wn = wid & 1;
    int row0 = blockIdx.x * 128, col0 = blockIdx.y * 128;
    scol[0][tid] = 0.f; scol[1][tid] = 0.f;
    uint32_t sbase = smem_u32(dsm);

    float acc[4][8][4] = {};
    gemm_core(g_xr, g_wmr, row0, col0, acc, dsm, sbase, tid, wm, wn, lr, lc);

    int bimg = row0 / HWp;
    int bsplit = (bimg + 1) * HWp;
    #pragma unroll
    for (int nj = 0; nj < 8; nj++) {
        int colr = wn*64 + nj*8 + lc*2;
        int col = col0 + colr;
        int p0 = P16(col), p1 = P16(col + 1);
        float s0[2] = {0.f, 0.f}, s1[2] = {0.f, 0.f};
        #pragma unroll
        for (int mi = 0; mi < 4; mi++) {
            int row = row0 + wm*64 + mi*16 + lr;
            size_t ra = (size_t)row*256, rb = (size_t)(row+8)*256;
            float c0x = acc[mi][nj][0], c0y = acc[mi][nj][1];
            float c1x = acc[mi][nj][2], c1y = acc[mi][nj][3];
            g_cc[ra + p0] = c0x;  g_cc[ra + p1] = c0y;
            g_cc[rb + p0] = c1x;  g_cc[rb + p1] = c1y;
            float h0x = g_hw[ra + p0], h0y = g_hw[ra + p1];
            float h1x = g_hw[rb + p0], h1y = g_hw[rb + p1];
            int r0 = (row >= bsplit) ? 1 : 0;
            int r1 = (row + 8 >= bsplit) ? 1 : 0;
            s0[r0] += c0x + h0x;  s1[r0] += c0y + h0y;
            s0[r1] += c1x + h1x;  s1[r1] += c1y + h1y;
        }
        atomicAdd(&scol[0][colr],   s0[0]);
        atomicAdd(&scol[0][colr+1], s1[0]);
        if (s0[1] != 0.f || s1[1] != 0.f) {
            atomicAdd(&scol[1][colr],   s0[1]);
            atomicAdd(&scol[1][colr+1], s1[1]);
        }
    }
    __syncthreads();
    atomicAdd(&g_asum[bimg*256 + col0 + tid], scol[0][tid]);
    float v1 = scol[1][tid];
    if (v1 != 0.f && bimg + 1 < Bc)
        atomicAdd(&g_asum[(bimg+1)*256 + col0 + tid], v1);
}

// ---------- reweight MLP + pairwise softmax; a0/a1 stored PERMUTED ----------
__global__ __launch_bounds__(256) void k_small2(const float* __restrict__ fc1w,
                                                const float* __restrict__ fc1b,
                                                const float* __restrict__ fc2w,
                                                const float* __restrict__ fc2b) {
    __shared__ float sm[256];
    __shared__ float h1[64];
    int b = blockIdx.x, tid = threadIdx.x;
    sm[tid] = g_asum[b*256 + tid] * (1.0f / (float)HWp);
    __syncthreads();
    int o = tid >> 2, qtr = tid & 3;
    {
        const float* w = &fc1w[(size_t)o*256 + qtr*64];
        const float* s = &sm[qtr*64];
        float p = 0.f;
        #pragma unroll 8
        for (int c = 0; c < 64; c++) p += s[c] * w[c];
        p += __shfl_xor_sync(0xffffffffu, p, 1);
        p += __shfl_xor_sync(0xffffffffu, p, 2);
        if (qtr == 0) {
            float a = p + fc1b[o];
            h1[o] = 0.5f * a * (1.0f + erff(a * 0.70710678118654752f));
        }
    }
    __syncthreads();
    int c = tid;
    float l0 = fc2b[2*c], l1 = fc2b[2*c+1];
    #pragma unroll 8
    for (int k = 0; k < 64; k++) {
        float hv = h1[k];
        l0 += hv * fc2w[(size_t)(2*c)*64 + k];
        l1 += hv * fc2w[(size_t)(2*c+1)*64 + k];
    }
    float m = fmaxf(l0, l1);
    float e0 = expf(l0 - m), e1 = expf(l1 - m);
    float s = 1.f / (e0 + e1);
    int pc = P16(c);
    g_a0[b*256 + pc] = e0 * s;
    g_a1[b*256 + pc] = e1 * s;
}

// ---------- final GEMM (full-width 128x256, fused y-assembly) ----------
__global__ __launch_bounds__(256) void k_mma_out3(const float* __restrict__ bp,
                                                  float* __restrict__ out) {
    extern __shared__ float dsm[];
    __shared__ float sa0[512], sa1[512];
    int tid = threadIdx.x, wid = tid >> 5, lane = tid & 31;
    int lr = lane >> 2, lc = lane & 3;
    int wm = wid >> 2, wn = wid & 3;
    int row0 = blockIdx.x * 128;
    int bimg = row0 / HWp;
    int bimg2 = (bimg + 1 < Bc) ? bimg + 1 : bimg;
    int bsplit = (bimg + 1) * HWp;
    sa0[tid]       = g_a0[bimg*256 + tid];
    sa1[tid]       = g_a1[bimg*256 + tid];
    sa0[256 + tid] = g_a0[bimg2*256 + tid];
    sa1[256 + tid] = g_a1[bimg2*256 + tid];
    uint32_t sbase = smem_u32(dsm);

    auto cpB = [&](int ch, int s) {
        uint32_t sb0 = sbase + (uint32_t)(s * STGO * 4);
        int k0 = ch * 32;
        #pragma unroll
        for (int i = 0; i < 8; i++) {
            int idx = tid + i*256, r = idx >> 3, q = idx & 7;
            cp16(sb0 + (uint32_t)((128*ST + r*ST + q*4)*4),
                 &g_wpr[(size_t)r*256 + k0 + q*4]);
        }
        CP_COMMIT();
    };
    float4 fh[4], fc[4];
    auto ldA = [&](int ch) {
        int k0 = ch * 32;
        #pragma unroll
        for (int i = 0; i < 4; i++) {
            int idx = tid + i*256, r = idx >> 3, q = idx & 7;
            size_t base = (size_t)(row0 + r)*256 + k0 + q*4;
            fh[i] = *(const float4*)&g_hw[base];
            fc[i] = *(const float4*)&g_cc[base];
        }
    };
    auto stA = [&](int ch, int s) {
        int k0 = ch * 32;
        #pragma unroll
        for (int i = 0; i < 4; i++) {
            int idx = tid + i*256, r = idx >> 3, q = idx & 7;
            int rel = ((row0 + r) >= bsplit) ? 256 : 0;
            int ki = rel + k0 + q*4;
            float4 v;
            v.x = rtf(fh[i].x * sa0[ki+0] + fc[i].x * sa1[ki+0]);
            v.y = rtf(fh[i].y * sa0[ki+1] + fc[i].y * sa1[ki+1]);
            v.z = rtf(fh[i].z * sa0[ki+2] + fc[i].z * sa1[ki+2]);
            v.w = rtf(fh[i].w * sa0[ki+3] + fc[i].w * sa1[ki+3]);
            *(float4*)&dsm[s*STGO + r*ST + q*4] = v;
        }
    };

    cpB(0, 0);
    cpB(1, 1);
    ldA(0);
    __syncthreads();
    stA(0, 0);
    ldA(1);

    float acc[4][8][4] = {};
    for (int ch = 0; ch < 8; ch++) {
        if (ch < 7) CP_WAIT1(); else CP_WAIT0();
        __syncthreads();
        const float* Ab = dsm + (ch & 1) * STGO;
        const float* Bb = Ab + 128*ST;
        #pragma unroll
        for (int g = 0; g < 2; g++) {
            float4 Alo[4], Ahi[4], Bv[8];
            #pragma unroll
            for (int mi = 0; mi < 4; mi++) {
                Alo[mi] = *(const float4*)&Ab[(wm*64 + mi*16 + lr)*ST + g*16 + lc*4];
                Ahi[mi] = *(const float4*)&Ab[(wm*64 + mi*16 + 8 + lr)*ST + g*16 + lc*4];
            }
            #pragma unroll
            for (int nj = 0; nj < 8; nj++)
                Bv[nj] = *(const float4*)&Bb[(wn*64 + nj*8 + lr)*ST + g*16 + lc*4];
            #pragma unroll
            for (int mi = 0; mi < 4; mi++) {
                uint32_t a0[4] = { __float_as_uint(Alo[mi].x), __float_as_uint(Ahi[mi].x),
                                   __float_as_uint(Alo[mi].y), __float_as_uint(Ahi[mi].y) };
                uint32_t a1[4] = { __float_as_uint(Alo[mi].z), __float_as_uint(Ahi[mi].z),
                                   __float_as_uint(Alo[mi].w), __float_as_uint(Ahi[mi].w) };
                #pragma unroll
                for (int nj = 0; nj < 8; nj++) {
                    mma_t(acc[mi][nj], a0, __float_as_uint(Bv[nj].x), __float_as_uint(Bv[nj].y));
                    mma_t(acc[mi][nj], a1, __float_as_uint(Bv[nj].z), __float_as_uint(Bv[nj].w));
                }
            }
            if (g == 0 && ch < 7) stA(ch + 1, (ch + 1) & 1);
        }
        if (ch < 6) ldA(ch + 2);
        __syncthreads();
        if (ch < 6) cpB(ch + 2, ch & 1);
    }

    #pragma unroll
    for (int nj = 0; nj < 8; nj++) {
        int col = wn*64 + nj*8 + lc*2;
        float bb0 = __ldg(&bp[col]), bb1 = __ldg(&bp[col+1]);
        #pragma unroll
        for (int mi = 0; mi < 4; mi++) {
            int row = row0 + wm*64 + mi*16 + lr;
            *(float2*)&out[(size_t)row*256 + col] =
                make_float2(acc[mi][nj][0] + bb0, acc[mi][nj][1] + bb1);
            *(float2*)&out[(size_t)(row+8)*256 + col] =
                make_float2(acc[mi][nj][2] + bb0, acc[mi][nj][3] + bb1);
        }
    }
}

extern "C" void kernel_launch(void* const* d_in, const int* in_sizes, int n_in,
                              void* d_out, int out_size) {
    const float* x        = (const float*)d_in[0];
    const float* conv1_w  = (const float*)d_in[1];
    const float* conv1_b  = (const float*)d_in[2];
    const float* bn_gamma = (const float*)d_in[3];
    const float* bn_beta  = (const float*)d_in[4];
    const float* conv2_w  = (const float*)d_in[5];
    const float* conv2_b  = (const float*)d_in[6];
    const float* mlp_c_w  = (const float*)d_in[7];
    const float* fc1_w    = (const float*)d_in[8];
    const float* fc1_b    = (const float*)d_in[9];
    const float* fc2_w    = (const float*)d_in[10];
    const float* fc2_b    = (const float*)d_in[11];
    const float* projcnn_w= (const float*)d_in[12];
    const float* projcnn_b= (const float*)d_in[13];
    float* out = (float*)d_out;

    cudaFuncSetAttribute(k_mma_c2,   cudaFuncAttributeMaxDynamicSharedMemorySize, DSMC);
    cudaFuncSetAttribute(k_mma_out3, cudaFuncAttributeMaxDynamicSharedMemorySize, DSMO);
    cudaFuncSetAttribute(k_mma_g1b,  cudaFuncAttributeMaxDynamicSharedMemorySize, DSG1);

    k_prep   <<<3136 + 36, 256>>>(x, mlp_c_w, projcnn_w, conv1_w);
    k_mma_g1b<<<Nn/128, 128, DSG1>>>(conv1_b);
    k_mma_kg <<<Nn/128, 256>>>(bn_gamma, bn_beta, conv2_w, conv2_b);
    k_invo6  <<<dim3(Bc*28, 8), 256>>>(x);
    k_mma_c2 <<<dim3(Nn/128, 2), 128, DSMC>>>();
    k_small2 <<<Bc, 256>>>(fc1_w, fc1_b, fc2_w, fc2_b);
    k_mma_out3<<<Nn/128, 256, DSMO>>>(projcnn_b, out);
}

// round 16
// speedup vs baseline: 1.1359x; 1.0872x over previous
#include <cuda_runtime.h>
#include <math.h>
#include <stdint.h>

#define Bc   16
#define Hh   56
#define Wd   56
#define Cch  256
#define C4c  64
#define GKK  72
#define HWp  (Hh*Wd)      // 3136
#define Nn   (Bc*HWp)     // 50176
#define EPSv 1e-5f

// permuted channel slot (involution: 4x4 transpose within 16-channel groups)
#define P16(c) (((c) & ~15) | ((((c) & 3) << 2) | (((c) >> 2) & 3)))

// ---- scratch (device globals) ----
__device__ float g_t[(size_t)Nn*C4c];
__device__ float g_wk[(size_t)Nn*GKK];
__device__ float g_hw[(size_t)Nn*Cch];    // channel-PERMUTED
__device__ float g_cc[(size_t)Nn*Cch];    // channel-PERMUTED
__device__ float g_xr[(size_t)Nn*Cch];    // x rounded+permuted
__device__ float g_wmr[Cch*Cch];          // mlp_c_w rounded+k-permuted
__device__ float g_wpr[Cch*Cch];          // projcnn_w rounded+k-permuted
__device__ float g_w1r[C4c*Cch];          // conv1_w rounded+k-permuted
__device__ float g_sum[C4c];
__device__ float g_sumsq[C4c];
__device__ float g_asum[Bc*Cch];          // ORIGINAL channel order (hw-part + cc-part)
__device__ float g_a0[Bc*Cch];            // channel-PERMUTED
__device__ float g_a1[Bc*Cch];            // channel-PERMUTED

// ================= helpers =================
__device__ __forceinline__ uint32_t f2tf(float f) {
    uint32_t r;
    asm("cvt.rna.tf32.f32 %0, %1;" : "=r"(r) : "f"(f));
    return r;
}
__device__ __forceinline__ float rtf(float f) { return __uint_as_float(f2tf(f)); }
__device__ __forceinline__ float4 tf4(float4 v) {
    v.x = rtf(v.x); v.y = rtf(v.y); v.z = rtf(v.z); v.w = rtf(v.w);
    return v;
}
__device__ __forceinline__ void mma_t(float* c, const uint32_t* a, uint32_t b0, uint32_t b1) {
    asm volatile(
        "mma.sync.aligned.m16n8k8.row.col.f32.tf32.tf32.f32 "
        "{%0,%1,%2,%3}, {%4,%5,%6,%7}, {%8,%9}, {%0,%1,%2,%3};"
        : "+f"(c[0]), "+f"(c[1]), "+f"(c[2]), "+f"(c[3])
        : "r"(a[0]), "r"(a[1]), "r"(a[2]), "r"(a[3]), "r"(b0), "r"(b1));
}
__device__ __forceinline__ uint32_t smem_u32(const void* p) {
    uint32_t a;
    asm("{ .reg .u64 t; cvta.to.shared.u64 t, %1; cvt.u32.u64 %0, t; }" : "=r"(a) : "l"(p));
    return a;
}
__device__ __forceinline__ void cp16(uint32_t dst, const void* src) {
    asm volatile("cp.async.cg.shared.global [%0], [%1], 16;" :: "r"(dst), "l"(src));
}
#define CP_COMMIT() asm volatile("cp.async.commit_group;")
#define CP_WAIT1()  asm volatile("cp.async.wait_group 1;")
#define CP_WAIT0()  asm volatile("cp.async.wait_group 0;")

#define SA 36            // legacy stride for kg kernel
#define ST 48            // permuted-layout row stride
#define STGF (256*ST)    // c stage: A 128 + B 128
#define DSMC (2*STGF*4)  // 98304
#define STG1 (192*ST)    // g1 stage: A 128 + B 64
#define DSG1 (2*STG1*4)  // 73728  (2-stage, 128 thr -> 3 CTAs/SM)
#define STGO (384*ST)    // out3 stage: A 128 + B 256
#define DSMO (2*STGO*4)  // 147456

// ============================ kernels ============================

// ---------- prep: round+permute x (blocks 0..3135), weights + zero (3136..) ----------
__global__ __launch_bounds__(256) void k_prep(const float* __restrict__ x,
                                              const float* __restrict__ wm,
                                              const float* __restrict__ wp,
                                              const float* __restrict__ w1) {
    int tid = threadIdx.x;
    int bx = blockIdx.x;
    if (bx < 3136) {
        size_t idx = (size_t)bx * 256 + tid;
        size_t base = idx * 16;
        float4 v0 = *(const float4*)&x[base];
        float4 v1 = *(const float4*)&x[base + 4];
        float4 v2 = *(const float4*)&x[base + 8];
        float4 v3 = *(const float4*)&x[base + 12];
        *(float4*)&g_xr[base]      = tf4(make_float4(v0.x, v1.x, v2.x, v3.x));
        *(float4*)&g_xr[base + 4]  = tf4(make_float4(v0.y, v1.y, v2.y, v3.y));
        *(float4*)&g_xr[base + 8]  = tf4(make_float4(v0.z, v1.z, v2.z, v3.z));
        *(float4*)&g_xr[base + 12] = tf4(make_float4(v0.w, v1.w, v2.w, v3.w));
        return;
    }
    if (bx == 3136) {
        if (tid < C4c) { g_sum[tid] = 0.f; g_sumsq[tid] = 0.f; }
        for (int i = tid; i < Bc*Cch; i += 256) g_asum[i] = 0.f;
    }
    int idx = (bx - 3136) * 256 + tid;
    if (idx >= 9216) return;
    const float* src;  float* dst;  size_t base;
    if (idx < 4096)       { src = wm; dst = g_wmr; base = (size_t)idx * 16; }
    else if (idx < 8192)  { src = wp; dst = g_wpr; base = (size_t)(idx - 4096) * 16; }
    else                  { src = w1; dst = g_w1r; base = (size_t)(idx - 8192) * 16; }
    float4 v0 = *(const float4*)&src[base];
    float4 v1 = *(const float4*)&src[base + 4];
    float4 v2 = *(const float4*)&src[base + 8];
    float4 v3 = *(const float4*)&src[base + 12];
    *(float4*)&dst[base]      = tf4(make_float4(v0.x, v1.x, v2.x, v3.x));
    *(float4*)&dst[base + 4]  = tf4(make_float4(v0.y, v1.y, v2.y, v3.y));
    *(float4*)&dst[base + 8]  = tf4(make_float4(v0.z, v1.z, v2.z, v3.z));
    *(float4*)&dst[base + 12] = tf4(make_float4(v0.w, v1.w, v2.w, v3.w));
}

// ---------- GEMM1 (2-stage cp.async, 128 thr): t = xr @ w1r^T + b ; fused BN stats ----------
__global__ __launch_bounds__(128) void k_mma_g1b(const float* __restrict__ b1) {
    extern __shared__ float dsm[];
    __shared__ float scol[64], ssq[64];
    int tid = threadIdx.x, wid = tid >> 5, lane = tid & 31;
    int lr = lane >> 2, lc = lane & 3;
    int wm = wid & 1, wn = wid >> 1;    // warp tile 64 x 32
    int row0 = blockIdx.x * 128;
    if (tid < 64) { scol[tid] = 0.f; ssq[tid] = 0.f; }
    uint32_t sbase = smem_u32(dsm);

    auto stage_cp = [&](int ch, int s) {
        uint32_t sb0 = sbase + (uint32_t)(s * STG1 * 4);
        int k0 = ch * 32;
        #pragma unroll
        for (int i = 0; i < 8; i++) {
            int idx = tid + i*128, r = idx >> 3, q = idx & 7;
            cp16(sb0 + (uint32_t)((r*ST + q*4)*4),
                 &g_xr[(size_t)(row0 + r)*256 + k0 + q*4]);
        }
        #pragma unroll
        for (int i = 0; i < 4; i++) {
            int idx = tid + i*128, r = idx >> 3, q = idx & 7;
            cp16(sb0 + (uint32_t)((128*ST + r*ST + q*4)*4),
                 &g_w1r[(size_t)r*256 + k0 + q*4]);
        }
        CP_COMMIT();
    };
    stage_cp(0, 0);
    stage_cp(1, 1);

    float acc[4][4][4] = {};
    for (int ch = 0; ch < 8; ch++) {
        if (ch < 7) CP_WAIT1(); else CP_WAIT0();
        __syncthreads();
        const float* Ab = dsm + (ch & 1) * STG1;
        const float* Bb = Ab + 128*ST;
        #pragma unroll
        for (int g = 0; g < 2; g++) {
            float4 Alo[4], Ahi[4], Bv[4];
            #pragma unroll
            for (int mi = 0; mi < 4; mi++) {
                Alo[mi] = *(const float4*)&Ab[(wm*64 + mi*16 + lr)*ST + g*16 + lc*4];
                Ahi[mi] = *(const float4*)&Ab[(wm*64 + mi*16 + 8 + lr)*ST + g*16 + lc*4];
            }
            #pragma unroll
            for (int nj = 0; nj < 4; nj++)
                Bv[nj] = *(const float4*)&Bb[(wn*32 + nj*8 + lr)*ST + g*16 + lc*4];
            #pragma unroll
            for (int mi = 0; mi < 4; mi++) {
                uint32_t a0[4] = { __float_as_uint(Alo[mi].x), __float_as_uint(Ahi[mi].x),
                                   __float_as_uint(Alo[mi].y), __float_as_uint(Ahi[mi].y) };
                uint32_t a1[4] = { __float_as_uint(Alo[mi].z), __float_as_uint(Ahi[mi].z),
                                   __float_as_uint(Alo[mi].w), __float_as_uint(Ahi[mi].w) };
                #pragma unroll
                for (int nj = 0; nj < 4; nj++) {
                    mma_t(acc[mi][nj], a0, __float_as_uint(Bv[nj].x), __float_as_uint(Bv[nj].y));
                    mma_t(acc[mi][nj], a1, __float_as_uint(Bv[nj].z), __float_as_uint(Bv[nj].w));
                }
            }
        }
        __syncthreads();
        if (ch < 6) stage_cp(ch + 2, ch & 1);
    }

    #pragma unroll
    for (int nj = 0; nj < 4; nj++) {
        int c0 = wn*32 + nj*8 + lc*2;
        float bb0 = __ldg(&b1[c0]), bb1 = __ldg(&b1[c0+1]);
        float s0 = 0.f, s1 = 0.f, q0 = 0.f, q1 = 0.f;
        #pragma unroll
        for (int mi = 0; mi < 4; mi++) {
            int row = row0 + wm*64 + mi*16 + lr;
            float v0 = acc[mi][nj][0] + bb0;
            float v1 = acc[mi][nj][1] + bb1;
            float v2 = acc[mi][nj][2] + bb0;
            float v3 = acc[mi][nj][3] + bb1;
            *(float2*)&g_t[(size_t)row*64 + c0]     = make_float2(v0, v1);
            *(float2*)&g_t[(size_t)(row+8)*64 + c0] = make_float2(v2, v3);
            s0 += v0 + v2; s1 += v1 + v3;
            q0 += v0*v0 + v2*v2; q1 += v1*v1 + v3*v3;
        }
        atomicAdd(&scol[c0], s0);   atomicAdd(&scol[c0+1], s1);
        atomicAdd(&ssq[c0],  q0);   atomicAdd(&ssq[c0+1],  q1);
    }
    __syncthreads();
    if (tid < 64) {
        atomicAdd(&g_sum[tid],   scol[tid]);
        atomicAdd(&g_sumsq[tid], ssq[tid]);
    }
}

// ---------- kernel-gen (tf32 MMA) ----------
__global__ __launch_bounds__(256) void k_mma_kg(const float* __restrict__ gamma,
                                                const float* __restrict__ beta,
                                                const float* __restrict__ w2,
                                                const float* __restrict__ b2) {
    __shared__ float As[128*SA];
    __shared__ float Bs[80*SA];
    __shared__ float sc[64], shf[64];
    int tid = threadIdx.x, wid = tid >> 5, lane = tid & 31;
    int lr = lane >> 2, lc = lane & 3;
    int wm = wid & 3, wn = wid >> 2;
    int row0 = blockIdx.x * 128;
    if (tid < 64) {
        const float invN = 1.0f / (float)Nn;
        float mu  = g_sum[tid] * invN;
        float var = g_sumsq[tid] * invN - mu * mu;
        float s = gamma[tid] * rsqrtf(var + EPSv);
        sc[tid]  = s;
        shf[tid] = beta[tid] - mu * s;
    }
    __syncthreads();

    float acc[2][5][4] = {};
    for (int ch = 0; ch < 2; ch++) {
        if (ch) __syncthreads();
        #pragma unroll
        for (int t = 0; t < 4; t++) {
            int idx = tid + t*256, r = idx >> 3, j = idx & 7;
            int c = ch*32 + j*4;
            float4 v = *(const float4*)&g_t[(size_t)(row0 + r)*64 + c];
            v.x = fmaxf(fmaf(v.x, sc[c+0], shf[c+0]), 0.f);
            v.y = fmaxf(fmaf(v.y, sc[c+1], shf[c+1]), 0.f);
            v.z = fmaxf(fmaf(v.z, sc[c+2], shf[c+2]), 0.f);
            v.w = fmaxf(fmaf(v.w, sc[c+3], shf[c+3]), 0.f);
            *(float4*)&As[r*SA + j*4] = tf4(v);
        }
        for (int idx = tid; idx < 80*8; idx += 256) {
            int r = idx >> 3, j = idx & 7;
            float4 v = make_float4(0.f, 0.f, 0.f, 0.f);
            if (r < 72) v = *(const float4*)&w2[(size_t)r*64 + ch*32 + j*4];
            *(float4*)&Bs[r*SA + j*4] = tf4(v);
        }
        __syncthreads();
        #pragma unroll
        for (int s = 0; s < 4; s++) {
            uint32_t a[2][4];
            #pragma unroll
            for (int mi = 0; mi < 2; mi++) {
                const float* Ap = &As[(wm*32 + mi*16 + lr)*SA + s*8 + lc];
                a[mi][0] = __float_as_uint(Ap[0]);
                a[mi][1] = __float_as_uint(Ap[8*SA]);
                a[mi][2] = __float_as_uint(Ap[4]);
                a[mi][3] = __float_as_uint(Ap[8*SA + 4]);
            }
            #pragma unroll
            for (int nj = 0; nj < 5; nj++) {
                const float* Bp = &Bs[(wn*40 + nj*8 + lr)*SA + s*8 + lc];
                uint32_t b0 = __float_as_uint(Bp[0]);
                uint32_t b1 = __float_as_uint(Bp[4]);
                mma_t(acc[0][nj], a[0], b0, b1);
                mma_t(acc[1][nj], a[1], b0, b1);
            }
        }
    }

    #pragma unroll
    for (int mi = 0; mi < 2; mi++) {
        int row = row0 + wm*32 + mi*16 + lr;
        #pragma unroll
        for (int nj = 0; nj < 5; nj++) {
            int col = wn*40 + nj*8 + lc*2;
            if (col < 72) {
                float bb0 = __ldg(&b2[col]), bb1 = __ldg(&b2[col+1]);
                *(float2*)&g_wk[(size_t)row*72 + col] =
                    make_float2(acc[mi][nj][0] + bb0, acc[mi][nj][1] + bb1);
                *(float2*)&g_wk[(size_t)(row+8)*72 + col] =
                    make_float2(acc[mi][nj][2] + bb0, acc[mi][nj][3] + bb1);
            }
        }
    }
}

// ---------- involution: channel-quad per thread + fused hw channel sums ----------
__global__ __launch_bounds__(256) void k_invo6b(const float* __restrict__ x) {
    __shared__ float xs[4][58][32];
    __shared__ float ws[2][56][9];
    __shared__ float hsum[32];
    int bi = blockIdx.x;               // b*28 + hp/2
    int g  = blockIdx.y;
    int b = bi / 28, hp = (bi % 28) * 2;
    int tid = threadIdx.x;

    if (tid < 32) hsum[tid] = 0.f;
    {
        int dy = tid >> 6, e = (tid >> 5) & 1, c = tid & 31;
        xs[dy][e ? 57 : 0][c] = 0.f;
    }
    for (int i = tid; i < 4*56*8; i += 256) {
        int c4 = i & 7, w = (i >> 3) % 56, dy = i / 448;
        int hh = hp + dy - 1;
        float4 v = make_float4(0.f, 0.f, 0.f, 0.f);
        if (hh >= 0 && hh < Hh)
            v = *(const float4*)&x[(((size_t)(b*Hh + hh))*Wd + w)*256 + g*32 + c4*4];
        *(float4*)&xs[dy][1 + w][c4*4] = v;
    }
    for (int i = tid; i < 2*56*9; i += 256) {
        int rr = i / (56*9), rem = i % (56*9), w = rem / 9, k = rem % 9;
        ws[rr][w][k] = g_wk[(((size_t)(b*Hh + hp + rr))*Wd + w)*72 + g*9 + k];
    }
    __syncthreads();

    int c4 = tid & 7, wq = tid >> 3;
    int slot = ((c4 & 4) << 2) | (c4 & 3);
    float4 hs = make_float4(0.f, 0.f, 0.f, 0.f);
    for (int w = wq; w < 56; w += 32) {
        float4 xv[4][3];
        #pragma unroll
        for (int dy = 0; dy < 4; dy++)
            #pragma unroll
            for (int dx = 0; dx < 3; dx++)
                xv[dy][dx] = *(const float4*)&xs[dy][w + dx][c4*4];
        #pragma unroll
        for (int rr = 0; rr < 2; rr++) {
            const float* wp9 = ws[rr][w];
            float4 a = make_float4(0.f, 0.f, 0.f, 0.f);
            #pragma unroll
            for (int dy = 0; dy < 3; dy++) {
                #pragma unroll
                for (int dx = 0; dx < 3; dx++) {
                    float wv = wp9[dy*3 + dx];
                    float4 xq = xv[rr + dy][dx];
                    a.x = fmaf(wv, xq.x, a.x);
                    a.y = fmaf(wv, xq.y, a.y);
                    a.z = fmaf(wv, xq.z, a.z);
                    a.w = fmaf(wv, xq.w, a.w);
                }
            }
            size_t ob = (((size_t)(b*Hh + hp + rr))*Wd + w)*256 + g*32 + slot;
            g_hw[ob + 0]  = a.x;
            g_hw[ob + 4]  = a.y;
            g_hw[ob + 8]  = a.z;
            g_hw[ob + 12] = a.w;
            hs.x += a.x; hs.y += a.y; hs.z += a.z; hs.w += a.w;
        }
    }
    // hw sums indexed by ORIGINAL channel = c4*4 + j
    atomicAdd(&hsum[c4*4 + 0], hs.x);
    atomicAdd(&hsum[c4*4 + 1], hs.y);
    atomicAdd(&hsum[c4*4 + 2], hs.z);
    atomicAdd(&hsum[c4*4 + 3], hs.w);
    __syncthreads();
    if (tid < 32) atomicAdd(&g_asum[b*256 + g*32 + tid], hsum[tid]);
}

// ================= cp.async 64x64-warp-tile GEMM core (128 thr, A128 B128) =================
__device__ __forceinline__ void gemm_core(const float* __restrict__ Ag,
                                          const float* __restrict__ Bg,
                                          int row0, int col0,
                                          float acc[4][8][4],
                                          float* dsm, uint32_t sbase,
                                          int tid, int wm, int wn, int lr, int lc) {
    auto stage_cp = [&](int ch, int s) {
        uint32_t sb0 = sbase + (uint32_t)(s * STGF * 4);
        int k0 = ch * 32;
        #pragma unroll
        for (int i = 0; i < 8; i++) {
            int idx = tid + i*128, r = idx >> 3, q = idx & 7;
            cp16(sb0 + (uint32_t)((r*ST + q*4)*4),
                 &Ag[(size_t)(row0 + r)*256 + k0 + q*4]);
        }
        #pragma unroll
        for (int i = 0; i < 8; i++) {
            int idx = tid + i*128, r = idx >> 3, q = idx & 7;
            cp16(sb0 + (uint32_t)((128*ST + r*ST + q*4)*4),
                 &Bg[(size_t)(col0 + r)*256 + k0 + q*4]);
        }
        CP_COMMIT();
    };
    stage_cp(0, 0);
    stage_cp(1, 1);

    for (int ch = 0; ch < 8; ch++) {
        if (ch < 7) CP_WAIT1(); else CP_WAIT0();
        __syncthreads();
        const float* Ab = dsm + (ch & 1) * STGF;
        const float* Bb = Ab + 128*ST;
        #pragma unroll
        for (int g = 0; g < 2; g++) {
            float4 Alo[4], Ahi[4], Bv[8];
            #pragma unroll
            for (int mi = 0; mi < 4; mi++) {
                Alo[mi] = *(const float4*)&Ab[(wm*64 + mi*16 + lr)*ST + g*16 + lc*4];
                Ahi[mi] = *(const float4*)&Ab[(wm*64 + mi*16 + 8 + lr)*ST + g*16 + lc*4];
            }
            #pragma unroll
            for (int nj = 0; nj < 8; nj++)
                Bv[nj] = *(const float4*)&Bb[(wn*64 + nj*8 + lr)*ST + g*16 + lc*4];
            #pragma unroll
            for (int mi = 0; mi < 4; mi++) {
                uint32_t a0[4] = { __float_as_uint(Alo[mi].x), __float_as_uint(Ahi[mi].x),
                                   __float_as_uint(Alo[mi].y), __float_as_uint(Ahi[mi].y) };
                uint32_t a1[4] = { __float_as_uint(Alo[mi].z), __float_as_uint(Ahi[mi].z),
                                   __float_as_uint(Alo[mi].w), __float_as_uint(Ahi[mi].w) };
                #pragma unroll
                for (int nj = 0; nj < 8; nj++) {
                    mma_t(acc[mi][nj], a0, __float_as_uint(Bv[nj].x), __float_as_uint(Bv[nj].y));
                    mma_t(acc[mi][nj], a1, __float_as_uint(Bv[nj].z), __float_as_uint(Bv[nj].w));
                }
            }
        }
        __syncthreads();
        if (ch < 6) stage_cp(ch + 2, ch & 1);
    }
}

// ---------- GEMM c = xr @ wmr^T ; PERMUTED cc ; cc-only column sums (no hw dependency) ----------
__global__ __launch_bounds__(128) void k_mma_c3() {
    extern __shared__ float dsm[];
    __shared__ float scol[2][128];
    int tid = threadIdx.x, wid = tid >> 5, lane = tid & 31;
    int lr = lane >> 2, lc = lane & 3;
    int wm = wid >> 1, wn = wid & 1;
    int row0 = blockIdx.x * 128, col0 = blockIdx.y * 128;
    scol[0][tid] = 0.f; scol[1][tid] = 0.f;
    uint32_t sbase = smem_u32(dsm);

    float acc[4][8][4] = {};
    gemm_core(g_xr, g_wmr, row0, col0, acc, dsm, sbase, tid, wm, wn, lr, lc);

    int bimg = row0 / HWp;
    int bsplit = (bimg + 1) * HWp;
    #pragma unroll
    for (int nj = 0; nj < 8; nj++) {
        int colr = wn*64 + nj*8 + lc*2;
        int col = col0 + colr;
        int p0 = P16(col), p1 = P16(col + 1);
        float s0[2] = {0.f, 0.f}, s1[2] = {0.f, 0.f};
        #pragma unroll
        for (int mi = 0; mi < 4; mi++) {
            int row = row0 + wm*64 + mi*16 + lr;
            size_t ra = (size_t)row*256, rb = (size_t)(row+8)*256;
            float c0x = acc[mi][nj][0], c0y = acc[mi][nj][1];
            float c1x = acc[mi][nj][2], c1y = acc[mi][nj][3];
            g_cc[ra + p0] = c0x;  g_cc[ra + p1] = c0y;
            g_cc[rb + p0] = c1x;  g_cc[rb + p1] = c1y;
            int r0 = (row >= bsplit) ? 1 : 0;
            int r1 = (row + 8 >= bsplit) ? 1 : 0;
            s0[r0] += c0x;  s1[r0] += c0y;
            s0[r1] += c1x;  s1[r1] += c1y;
        }
        atomicAdd(&scol[0][colr],   s0[0]);
        atomicAdd(&scol[0][colr+1], s1[0]);
        if (s0[1] != 0.f || s1[1] != 0.f) {
            atomicAdd(&scol[1][colr],   s0[1]);
            atomicAdd(&scol[1][colr+1], s1[1]);
        }
    }
    __syncthreads();
    atomicAdd(&g_asum[bimg*256 + col0 + tid], scol[0][tid]);
    float v1 = scol[1][tid];
    if (v1 != 0.f && bimg + 1 < Bc)
        atomicAdd(&g_asum[(bimg+1)*256 + col0 + tid], v1);
}

// ---------- reweight MLP + pairwise softmax; a0/a1 stored PERMUTED ----------
__global__ __launch_bounds__(256) void k_small2(const float* __restrict__ fc1w,
                                                const float* __restrict__ fc1b,
                                                const float* __restrict__ fc2w,
                                                const float* __restrict__ fc2b) {
    __shared__ float sm[256];
    __shared__ float h1[64];
    int b = blockIdx.x, tid = threadIdx.x;
    sm[tid] = g_asum[b*256 + tid] * (1.0f / (float)HWp);
    __syncthreads();
    int o = tid >> 2, qtr = tid & 3;
    {
        const float* w = &fc1w[(size_t)o*256 + qtr*64];
        const float* s = &sm[qtr*64];
        float p = 0.f;
        #pragma unroll 8
        for (int c = 0; c < 64; c++) p += s[c] * w[c];
        p += __shfl_xor_sync(0xffffffffu, p, 1);
        p += __shfl_xor_sync(0xffffffffu, p, 2);
        if (qtr == 0) {
            float a = p + fc1b[o];
            h1[o] = 0.5f * a * (1.0f + erff(a * 0.70710678118654752f));
        }
    }
    __syncthreads();
    int c = tid;
    float l0 = fc2b[2*c], l1 = fc2b[2*c+1];
    #pragma unroll 8
    for (int k = 0; k < 64; k++) {
        float hv = h1[k];
        l0 += hv * fc2w[(size_t)(2*c)*64 + k];
        l1 += hv * fc2w[(size_t)(2*c+1)*64 + k];
    }
    float m = fmaxf(l0, l1);
    float e0 = expf(l0 - m), e1 = expf(l1 - m);
    float s = 1.f / (e0 + e1);
    int pc = P16(c);
    g_a0[b*256 + pc] = e0 * s;
    g_a1[b*256 + pc] = e1 * s;
}

// ---------- final GEMM (full-width 128x256, fused y-assembly) ----------
__global__ __launch_bounds__(256) void k_mma_out3(const float* __restrict__ bp,
                                                  float* __restrict__ out) {
    extern __shared__ float dsm[];
    __shared__ float sa0[512], sa1[512];
    int tid = threadIdx.x, wid = tid >> 5, lane = tid & 31;
    int lr = lane >> 2, lc = lane & 3;
    int wm = wid >> 2, wn = wid & 3;
    int row0 = blockIdx.x * 128;
    int bimg = row0 / HWp;
    int bimg2 = (bimg + 1 < Bc) ? bimg + 1 : bimg;
    int bsplit = (bimg + 1) * HWp;
    sa0[tid]       = g_a0[bimg*256 + tid];
    sa1[tid]       = g_a1[bimg*256 + tid];
    sa0[256 + tid] = g_a0[bimg2*256 + tid];
    sa1[256 + tid] = g_a1[bimg2*256 + tid];
    uint32_t sbase = smem_u32(dsm);

    auto cpB = [&](int ch, int s) {
        uint32_t sb0 = sbase + (uint32_t)(s * STGO * 4);
        int k0 = ch * 32;
        #pragma unroll
        for (int i = 0; i < 8; i++) {
            int idx = tid + i*256, r = idx >> 3, q = idx & 7;
            cp16(sb0 + (uint32_t)((128*ST + r*ST + q*4)*4),
                 &g_wpr[(size_t)r*256 + k0 + q*4]);
        }
        CP_COMMIT();
    };
    float4 fh[4], fc[4];
    auto ldA = [&](int ch) {
        int k0 = ch * 32;
        #pragma unroll
        for (int i = 0; i < 4; i++) {
            int idx = tid + i*256, r = idx >> 3, q = idx & 7;
            size_t base = (size_t)(row0 + r)*256 + k0 + q*4;
            fh[i] = *(const float4*)&g_hw[base];
            fc[i] = *(const float4*)&g_cc[base];
        }
    };
    auto stA = [&](int ch, int s) {
        int k0 = ch * 32;
        #pragma unroll
        for (int i = 0; i < 4; i++) {
            int idx = tid + i*256, r = idx >> 3, q = idx & 7;
            int rel = ((row0 + r) >= bsplit) ? 256 : 0;
            int ki = rel + k0 + q*4;
            float4 v;
            v.x = rtf(fh[i].x * sa0[ki+0] + fc[i].x * sa1[ki+0]);
            v.y = rtf(fh[i].y * sa0[ki+1] + fc[i].y * sa1[ki+1]);
            v.z = rtf(fh[i].z * sa0[ki+2] + fc[i].z * sa1[ki+2]);
            v.w = rtf(fh[i].w * sa0[ki+3] + fc[i].w * sa1[ki+3]);
            *(float4*)&dsm[s*STGO + r*ST + q*4] = v;
        }
    };

    cpB(0, 0);
    cpB(1, 1);
    ldA(0);
    __syncthreads();
    stA(0, 0);
    ldA(1);

    float acc[4][8][4] = {};
    for (int ch = 0; ch < 8; ch++) {
        if (ch < 7) CP_WAIT1(); else CP_WAIT0();
        __syncthreads();
        const float* Ab = dsm + (ch & 1) * STGO;
        const float* Bb = Ab + 128*ST;
        #pragma unroll
        for (int g = 0; g < 2; g++) {
            float4 Alo[4], Ahi[4], Bv[8];
            #pragma unroll
            for (int mi = 0; mi < 4; mi++) {
                Alo[mi] = *(const float4*)&Ab[(wm*64 + mi*16 + lr)*ST + g*16 + lc*4];
                Ahi[mi] = *(const float4*)&Ab[(wm*64 + mi*16 + 8 + lr)*ST + g*16 + lc*4];
            }
            #pragma unroll
            for (int nj = 0; nj < 8; nj++)
                Bv[nj] = *(const float4*)&Bb[(wn*64 + nj*8 + lr)*ST + g*16 + lc*4];
            #pragma unroll
            for (int mi = 0; mi < 4; mi++) {
                uint32_t a0[4] = { __float_as_uint(Alo[mi].x), __float_as_uint(Ahi[mi].x),
                                   __float_as_uint(Alo[mi].y), __float_as_uint(Ahi[mi].y) };
                uint32_t a1[4] = { __float_as_uint(Alo[mi].z), __float_as_uint(Ahi[mi].z),
                                   __float_as_uint(Alo[mi].w), __float_as_uint(Ahi[mi].w) };
                #pragma unroll
                for (int nj = 0; nj < 8; nj++) {
                    mma_t(acc[mi][nj], a0, __float_as_uint(Bv[nj].x), __float_as_uint(Bv[nj].y));
                    mma_t(acc[mi][nj], a1, __float_as_uint(Bv[nj].z), __float_as_uint(Bv[nj].w));
                }
            }
            if (g == 0 && ch < 7) stA(ch + 1, (ch + 1) & 1);
        }
        if (ch < 6) ldA(ch + 2);
        __syncthreads();
        if (ch < 6) cpB(ch + 2, ch & 1);
    }

    #pragma unroll
    for (int nj = 0; nj < 8; nj++) {
        int col = wn*64 + nj*8 + lc*2;
        float bb0 = __ldg(&bp[col]), bb1 = __ldg(&bp[col+1]);
        #pragma unroll
        for (int mi = 0; mi < 4; mi++) {
            int row = row0 + wm*64 + mi*16 + lr;
            *(float2*)&out[(size_t)row*256 + col] =
                make_float2(acc[mi][nj][0] + bb0, acc[mi][nj][1] + bb1);
            *(float2*)&out[(size_t)(row+8)*256 + col] =
                make_float2(acc[mi][nj][2] + bb0, acc[mi][nj][3] + bb1);
        }
    }
}

extern "C" void kernel_launch(void* const* d_in, const int* in_sizes, int n_in,
                              void* d_out, int out_size) {
    const float* x        = (const float*)d_in[0];
    const float* conv1_w  = (const float*)d_in[1];
    const float* conv1_b  = (const float*)d_in[2];
    const float* bn_gamma = (const float*)d_in[3];
    const float* bn_beta  = (const float*)d_in[4];
    const float* conv2_w  = (const float*)d_in[5];
    const float* conv2_b  = (const float*)d_in[6];
    const float* mlp_c_w  = (const float*)d_in[7];
    const float* fc1_w    = (const float*)d_in[8];
    const float* fc1_b    = (const float*)d_in[9];
    const float* fc2_w    = (const float*)d_in[10];
    const float* fc2_b    = (const float*)d_in[11];
    const float* projcnn_w= (const float*)d_in[12];
    const float* projcnn_b= (const float*)d_in[13];
    float* out = (float*)d_out;

    // one-time resources (created on the first, non-captured correctness call)
    static cudaStream_t s2 = nullptr;
    static cudaEvent_t evF = nullptr, evJ = nullptr;
    if (s2 == nullptr) {
        cudaStreamCreateWithFlags(&s2, cudaStreamNonBlocking);
        cudaEventCreateWithFlags(&evF, cudaEventDisableTiming);
        cudaEventCreateWithFlags(&evJ, cudaEventDisableTiming);
        cudaFuncSetAttribute(k_mma_c3,   cudaFuncAttributeMaxDynamicSharedMemorySize, DSMC);
        cudaFuncSetAttribute(k_mma_out3, cudaFuncAttributeMaxDynamicSharedMemorySize, DSMO);
        cudaFuncSetAttribute(k_mma_g1b,  cudaFuncAttributeMaxDynamicSharedMemorySize, DSG1);
    }

    k_prep   <<<3136 + 36, 256>>>(x, mlp_c_w, projcnn_w, conv1_w);

    // fork: c (xr @ wmr) depends only on prep
    cudaEventRecord(evF, 0);
    cudaStreamWaitEvent(s2, evF, 0);
    k_mma_c3 <<<dim3(Nn/128, 2), 128, DSMC, s2>>>();
    cudaEventRecord(evJ, s2);

    // main chain: g1b -> kg -> invo (with fused hw sums)
    k_mma_g1b<<<Nn/128, 128, DSG1>>>(conv1_b);
    k_mma_kg <<<Nn/128, 256>>>(bn_gamma, bn_beta, conv2_w, conv2_b);
    k_invo6b <<<dim3(Bc*28, 8), 256>>>(x);

    // join: small2 needs both hw sums (invo) and cc sums (c3)
    cudaStreamWaitEvent(0, evJ, 0);
    k_small2 <<<Bc, 256>>>(fc1_w, fc1_b, fc2_w, fc2_b);
    k_mma_out3<<<Nn/128, 256, DSMO>>>(projcnn_b, out);
}

// round 17
// speedup vs baseline: 1.2722x; 1.1199x over previous
#include <cuda_runtime.h>
#include <cuda_fp16.h>
#include <math.h>
#include <stdint.h>

#define Bc   16
#define Hh   56
#define Wd   56
#define Cch  256
#define C4c  64
#define GKK  72
#define HWp  (Hh*Wd)      // 3136
#define Nn   (Bc*HWp)     // 50176
#define EPSv 1e-5f

// permuted channel slot (involution: 4x4 transpose within 16-channel groups)
#define P16(c) (((c) & ~15) | ((((c) & 3) << 2) | (((c) >> 2) & 3)))

// ---- scratch (device globals) ----
__device__ float  g_t[(size_t)Nn*C4c];
__device__ float  g_wk[(size_t)Nn*GKK];
__device__ float  g_hw[(size_t)Nn*Cch];    // channel-PERMUTED (P16)
__device__ float  g_cc[(size_t)Nn*Cch];    // channel-PERMUTED (P16)
__device__ __half g_xh[(size_t)Nn*Cch];    // x, fp16, per-32k slot layout
__device__ __half g_wmh[Cch*Cch];          // mlp_c_w, fp16 slot layout
__device__ __half g_w1h[C4c*Cch];          // conv1_w, fp16 slot layout
__device__ float  g_wpr[Cch*Cch];          // projcnn_w rounded+P16-k-permuted (float)
__device__ float  g_sum[C4c];
__device__ float  g_sumsq[C4c];
__device__ float  g_asum[Bc*Cch];          // ORIGINAL channel order (hw-part + cc-part)
__device__ float  g_a0[Bc*Cch];            // channel-PERMUTED
__device__ float  g_a1[Bc*Cch];            // channel-PERMUTED

// ================= helpers =================
__device__ __forceinline__ uint32_t f2tf(float f) {
    uint32_t r;
    asm("cvt.rna.tf32.f32 %0, %1;" : "=r"(r) : "f"(f));
    return r;
}
__device__ __forceinline__ float rtf(float f) { return __uint_as_float(f2tf(f)); }
__device__ __forceinline__ float4 tf4(float4 v) {
    v.x = rtf(v.x); v.y = rtf(v.y); v.z = rtf(v.z); v.w = rtf(v.w);
    return v;
}
__device__ __forceinline__ void mma_t(float* c, const uint32_t* a, uint32_t b0, uint32_t b1) {
    asm volatile(
        "mma.sync.aligned.m16n8k8.row.col.f32.tf32.tf32.f32 "
        "{%0,%1,%2,%3}, {%4,%5,%6,%7}, {%8,%9}, {%0,%1,%2,%3};"
        : "+f"(c[0]), "+f"(c[1]), "+f"(c[2]), "+f"(c[3])
        : "r"(a[0]), "r"(a[1]), "r"(a[2]), "r"(a[3]), "r"(b0), "r"(b1));
}
__device__ __forceinline__ void mma_h(float* c, uint32_t a0, uint32_t a1, uint32_t a2, uint32_t a3,
                                      uint32_t b0, uint32_t b1) {
    asm volatile(
        "mma.sync.aligned.m16n8k16.row.col.f32.f16.f16.f32 "
        "{%0,%1,%2,%3}, {%4,%5,%6,%7}, {%8,%9}, {%0,%1,%2,%3};"
        : "+f"(c[0]), "+f"(c[1]), "+f"(c[2]), "+f"(c[3])
        : "r"(a0), "r"(a1), "r"(a2), "r"(a3), "r"(b0), "r"(b1));
}
__device__ __forceinline__ uint32_t smem_u32(const void* p) {
    uint32_t a;
    asm("{ .reg .u64 t; cvta.to.shared.u64 t, %1; cvt.u32.u64 %0, t; }" : "=r"(a) : "l"(p));
    return a;
}
__device__ __forceinline__ void cp16(uint32_t dst, const void* src) {
    asm volatile("cp.async.cg.shared.global [%0], [%1], 16;" :: "r"(dst), "l"(src));
}
#define CP_COMMIT() asm volatile("cp.async.commit_group;")
#define CP_WAIT2()  asm volatile("cp.async.wait_group 2;")
#define CP_WAIT1()  asm volatile("cp.async.wait_group 1;")
#define CP_WAIT0()  asm volatile("cp.async.wait_group 0;")

#define SA 36             // stride for kg kernel
#define ST 48             // float permuted-layout row stride (out3)
#define STGO (384*ST)     // out3 stage: A 128 + B 256
#define DSMO (2*STGO*4)   // 147456
#define CHH  32           // halves per row per k32 chunk
#define STGH (256*CHH)    // c3h stage halves (A128 + B128)
#define DSMH (3*STGH*2)   // 49152
#define STG1H (192*CHH)   // g1h stage halves (A128 + B64)
#define DSG1H (3*STG1H*2) // 36864

// fp16 slot conversion: 32 consecutive k floats -> 32 halves in fragment-slot order
__device__ __forceinline__ void conv32h(const float* __restrict__ src, __half* __restrict__ dst) {
    float4 f[8];
    #pragma unroll
    for (int j = 0; j < 8; j++) f[j] = *(const float4*)&src[j*4];
    uint32_t w[16];
    #pragma unroll
    for (int c = 0; c < 4; c++) {
        #pragma unroll
        for (int a = 0; a < 4; a++) {
            float4 ff = f[(c >> 1) + 2*a];
            float lo = (c & 1) ? ff.z : ff.x;
            float hi = (c & 1) ? ff.w : ff.y;
            __half2 h = __floats2half2_rn(lo, hi);
            w[4*c + a] = *(uint32_t*)&h;
        }
    }
    #pragma unroll
    for (int i = 0; i < 4; i++) {
        uint4 u = make_uint4(w[4*i], w[4*i+1], w[4*i+2], w[4*i+3]);
        *(uint4*)&dst[i*8] = u;
    }
}

// ============================ kernels ============================

// ---------- prep: x->half slots, wpr float P16, wm/w1 half slots, zero ----------
__global__ __launch_bounds__(256) void k_prep(const float* __restrict__ x,
                                              const float* __restrict__ wm,
                                              const float* __restrict__ wp,
                                              const float* __restrict__ w1) {
    int tid = threadIdx.x;
    int bx = blockIdx.x;
    if (bx < 1568) {                           // x: 401408 chunks of 32
        size_t idx = (size_t)bx * 256 + tid;
        conv32h(&x[idx * 32], &g_xh[idx * 32]);
        return;
    }
    if (bx < 1584) {                           // wpr: float, P16 k-permute (old path)
        int idx = (bx - 1568) * 256 + tid;     // 0..4095 16-groups
        size_t base = (size_t)idx * 16;
        float4 v0 = *(const float4*)&wp[base];
        float4 v1 = *(const float4*)&wp[base + 4];
        float4 v2 = *(const float4*)&wp[base + 8];
        float4 v3 = *(const float4*)&wp[base + 12];
        *(float4*)&g_wpr[base]      = tf4(make_float4(v0.x, v1.x, v2.x, v3.x));
        *(float4*)&g_wpr[base + 4]  = tf4(make_float4(v0.y, v1.y, v2.y, v3.y));
        *(float4*)&g_wpr[base + 8]  = tf4(make_float4(v0.z, v1.z, v2.z, v3.z));
        *(float4*)&g_wpr[base + 12] = tf4(make_float4(v0.w, v1.w, v2.w, v3.w));
        return;
    }
    if (bx < 1594) {                           // wm (2048 chunks) + w1 (512 chunks)
        int idx = (bx - 1584) * 256 + tid;     // 0..2559
        if (idx < 2048) conv32h(&wm[(size_t)idx * 32], &g_wmh[(size_t)idx * 32]);
        else { int j = idx - 2048; conv32h(&w1[(size_t)j * 32], &g_w1h[(size_t)j * 32]); }
        return;
    }
    // zero accumulators
    if (tid < C4c) { g_sum[tid] = 0.f; g_sumsq[tid] = 0.f; }
    for (int i = tid; i < Bc*Cch; i += 256) g_asum[i] = 0.f;
}

// ---------- GEMM1 (fp16, 3-stage cp.async, 128 thr): t = x @ conv1_w^T + b ; BN stats ----------
__global__ __launch_bounds__(128) void k_mma_g1h(const float* __restrict__ b1) {
    extern __shared__ __half hsm[];
    __shared__ float scol[64], ssq[64];
    int tid = threadIdx.x, wid = tid >> 5, lane = tid & 31;
    int lr = lane >> 2, lc = lane & 3;
    int wm = wid & 1, wn = wid >> 1;    // warp tile 64 x 32
    int row0 = blockIdx.x * 128;
    if (tid < 64) { scol[tid] = 0.f; ssq[tid] = 0.f; }
    uint32_t sbase = smem_u32(hsm);

    auto stage_cp = [&](int ch, int s) {
        uint32_t sb0 = sbase + (uint32_t)(s * STG1H * 2);
        int k0 = ch * 32;
        #pragma unroll
        for (int i = 0; i < 4; i++) {
            int idx = tid + i*128, r = idx >> 2, q = idx & 3;
            cp16(sb0 + (uint32_t)(r*64 + q*16),
                 &g_xh[(size_t)(row0 + r)*256 + k0 + q*8]);
        }
        #pragma unroll
        for (int i = 0; i < 2; i++) {
            int idx = tid + i*128, r = idx >> 2, q = idx & 3;
            cp16(sb0 + (uint32_t)(128*64 + r*64 + q*16),
                 &g_w1h[(size_t)r*256 + k0 + q*8]);
        }
        CP_COMMIT();
    };
    stage_cp(0, 0); stage_cp(1, 1); stage_cp(2, 2);

    float acc[4][4][4] = {};
    for (int ch = 0; ch < 8; ch++) {
        if (ch < 6) CP_WAIT2(); else if (ch == 6) CP_WAIT1(); else CP_WAIT0();
        __syncthreads();
        const __half* Ab = hsm + (ch % 3) * STG1H;
        const __half* Bb = Ab + 128*CHH;
        uint4 Alo[4], Ahi[4], Bv[4];
        #pragma unroll
        for (int mi = 0; mi < 4; mi++) {
            Alo[mi] = *(const uint4*)&Ab[(wm*64 + mi*16 + lr)*CHH + lc*8];
            Ahi[mi] = *(const uint4*)&Ab[(wm*64 + mi*16 + 8 + lr)*CHH + lc*8];
        }
        #pragma unroll
        for (int nj = 0; nj < 4; nj++)
            Bv[nj] = *(const uint4*)&Bb[(wn*32 + nj*8 + lr)*CHH + lc*8];
        #pragma unroll
        for (int mi = 0; mi < 4; mi++) {
            #pragma unroll
            for (int nj = 0; nj < 4; nj++) {
                mma_h(acc[mi][nj], Alo[mi].x, Ahi[mi].x, Alo[mi].y, Ahi[mi].y, Bv[nj].x, Bv[nj].y);
                mma_h(acc[mi][nj], Alo[mi].z, Ahi[mi].z, Alo[mi].w, Ahi[mi].w, Bv[nj].z, Bv[nj].w);
            }
        }
        __syncthreads();
        if (ch < 5) stage_cp(ch + 3, ch % 3);
    }

    #pragma unroll
    for (int nj = 0; nj < 4; nj++) {
        int c0 = wn*32 + nj*8 + lc*2;
        float bb0 = __ldg(&b1[c0]), bb1 = __ldg(&b1[c0+1]);
        float s0 = 0.f, s1 = 0.f, q0 = 0.f, q1 = 0.f;
        #pragma unroll
        for (int mi = 0; mi < 4; mi++) {
            int row = row0 + wm*64 + mi*16 + lr;
            float v0 = acc[mi][nj][0] + bb0;
            float v1 = acc[mi][nj][1] + bb1;
            float v2 = acc[mi][nj][2] + bb0;
            float v3 = acc[mi][nj][3] + bb1;
            *(float2*)&g_t[(size_t)row*64 + c0]     = make_float2(v0, v1);
            *(float2*)&g_t[(size_t)(row+8)*64 + c0] = make_float2(v2, v3);
            s0 += v0 + v2; s1 += v1 + v3;
            q0 += v0*v0 + v2*v2; q1 += v1*v1 + v3*v3;
        }
        atomicAdd(&scol[c0], s0);   atomicAdd(&scol[c0+1], s1);
        atomicAdd(&ssq[c0],  q0);   atomicAdd(&ssq[c0+1],  q1);
    }
    __syncthreads();
    if (tid < 64) {
        atomicAdd(&g_sum[tid],   scol[tid]);
        atomicAdd(&g_sumsq[tid], ssq[tid]);
    }
}

// ---------- kernel-gen (tf32 MMA, unchanged) ----------
__global__ __launch_bounds__(256) void k_mma_kg(const float* __restrict__ gamma,
                                                const float* __restrict__ beta,
                                                const float* __restrict__ w2,
                                                const float* __restrict__ b2) {
    __shared__ float As[128*SA];
    __shared__ float Bs[80*SA];
    __shared__ float sc[64], shf[64];
    int tid = threadIdx.x, wid = tid >> 5, lane = tid & 31;
    int lr = lane >> 2, lc = lane & 3;
    int wm = wid & 3, wn = wid >> 2;
    int row0 = blockIdx.x * 128;
    if (tid < 64) {
        const float invN = 1.0f / (float)Nn;
        float mu  = g_sum[tid] * invN;
        float var = g_sumsq[tid] * invN - mu * mu;
        float s = gamma[tid] * rsqrtf(var + EPSv);
        sc[tid]  = s;
        shf[tid] = beta[tid] - mu * s;
    }
    __syncthreads();

    float acc[2][5][4] = {};
    for (int ch = 0; ch < 2; ch++) {
        if (ch) __syncthreads();
        #pragma unroll
        for (int t = 0; t < 4; t++) {
            int idx = tid + t*256, r = idx >> 3, j = idx & 7;
            int c = ch*32 + j*4;
            float4 v = *(const float4*)&g_t[(size_t)(row0 + r)*64 + c];
            v.x = fmaxf(fmaf(v.x, sc[c+0], shf[c+0]), 0.f);
            v.y = fmaxf(fmaf(v.y, sc[c+1], shf[c+1]), 0.f);
            v.z = fmaxf(fmaf(v.z, sc[c+2], shf[c+2]), 0.f);
            v.w = fmaxf(fmaf(v.w, sc[c+3], shf[c+3]), 0.f);
            *(float4*)&As[r*SA + j*4] = tf4(v);
        }
        for (int idx = tid; idx < 80*8; idx += 256) {
            int r = idx >> 3, j = idx & 7;
            float4 v = make_float4(0.f, 0.f, 0.f, 0.f);
            if (r < 72) v = *(const float4*)&w2[(size_t)r*64 + ch*32 + j*4];
            *(float4*)&Bs[r*SA + j*4] = tf4(v);
        }
        __syncthreads();
        #pragma unroll
        for (int s = 0; s < 4; s++) {
            uint32_t a[2][4];
            #pragma unroll
            for (int mi = 0; mi < 2; mi++) {
                const float* Ap = &As[(wm*32 + mi*16 + lr)*SA + s*8 + lc];
                a[mi][0] = __float_as_uint(Ap[0]);
                a[mi][1] = __float_as_uint(Ap[8*SA]);
                a[mi][2] = __float_as_uint(Ap[4]);
                a[mi][3] = __float_as_uint(Ap[8*SA + 4]);
            }
            #pragma unroll
            for (int nj = 0; nj < 5; nj++) {
                const float* Bp = &Bs[(wn*40 + nj*8 + lr)*SA + s*8 + lc];
                uint32_t b0 = __float_as_uint(Bp[0]);
                uint32_t b1 = __float_as_uint(Bp[4]);
                mma_t(acc[0][nj], a[0], b0, b1);
                mma_t(acc[1][nj], a[1], b0, b1);
            }
        }
    }

    #pragma unroll
    for (int mi = 0; mi < 2; mi++) {
        int row = row0 + wm*32 + mi*16 + lr;
        #pragma unroll
        for (int nj = 0; nj < 5; nj++) {
            int col = wn*40 + nj*8 + lc*2;
            if (col < 72) {
                float bb0 = __ldg(&b2[col]), bb1 = __ldg(&b2[col+1]);
                *(float2*)&g_wk[(size_t)row*72 + col] =
                    make_float2(acc[mi][nj][0] + bb0, acc[mi][nj][1] + bb1);
                *(float2*)&g_wk[(size_t)(row+8)*72 + col] =
                    make_float2(acc[mi][nj][2] + bb0, acc[mi][nj][3] + bb1);
            }
        }
    }
}

// ---------- involution: channel-quad per thread + fused hw channel sums ----------
__global__ __launch_bounds__(256) void k_invo6b(const float* __restrict__ x) {
    __shared__ float xs[4][58][32];
    __shared__ float ws[2][56][9];
    __shared__ float hsum[32];
    int bi = blockIdx.x;               // b*28 + hp/2
    int g  = blockIdx.y;
    int b = bi / 28, hp = (bi % 28) * 2;
    int tid = threadIdx.x;

    if (tid < 32) hsum[tid] = 0.f;
    {
        int dy = tid >> 6, e = (tid >> 5) & 1, c = tid & 31;
        xs[dy][e ? 57 : 0][c] = 0.f;
    }
    for (int i = tid; i < 4*56*8; i += 256) {
        int c4 = i & 7, w = (i >> 3) % 56, dy = i / 448;
        int hh = hp + dy - 1;
        float4 v = make_float4(0.f, 0.f, 0.f, 0.f);
        if (hh >= 0 && hh < Hh)
            v = *(const float4*)&x[(((size_t)(b*Hh + hh))*Wd + w)*256 + g*32 + c4*4];
        *(float4*)&xs[dy][1 + w][c4*4] = v;
    }
    for (int i = tid; i < 2*56*9; i += 256) {
        int rr = i / (56*9), rem = i % (56*9), w = rem / 9, k = rem % 9;
        ws[rr][w][k] = g_wk[(((size_t)(b*Hh + hp + rr))*Wd + w)*72 + g*9 + k];
    }
    __syncthreads();

    int c4 = tid & 7, wq = tid >> 3;
    int slot = ((c4 & 4) << 2) | (c4 & 3);
    float4 hs = make_float4(0.f, 0.f, 0.f, 0.f);
    for (int w = wq; w < 56; w += 32) {
        float4 xv[4][3];
        #pragma unroll
        for (int dy = 0; dy < 4; dy++)
            #pragma unroll
            for (int dx = 0; dx < 3; dx++)
                xv[dy][dx] = *(const float4*)&xs[dy][w + dx][c4*4];
        #pragma unroll
        for (int rr = 0; rr < 2; rr++) {
            const float* wp9 = ws[rr][w];
            float4 a = make_float4(0.f, 0.f, 0.f, 0.f);
            #pragma unroll
            for (int dy = 0; dy < 3; dy++) {
                #pragma unroll
                for (int dx = 0; dx < 3; dx++) {
                    float wv = wp9[dy*3 + dx];
                    float4 xq = xv[rr + dy][dx];
                    a.x = fmaf(wv, xq.x, a.x);
                    a.y = fmaf(wv, xq.y, a.y);
                    a.z = fmaf(wv, xq.z, a.z);
                    a.w = fmaf(wv, xq.w, a.w);
                }
            }
            size_t ob = (((size_t)(b*Hh + hp + rr))*Wd + w)*256 + g*32 + slot;
            g_hw[ob + 0]  = a.x;
            g_hw[ob + 4]  = a.y;
            g_hw[ob + 8]  = a.z;
            g_hw[ob + 12] = a.w;
            hs.x += a.x; hs.y += a.y; hs.z += a.z; hs.w += a.w;
        }
    }
    atomicAdd(&hsum[c4*4 + 0], hs.x);
    atomicAdd(&hsum[c4*4 + 1], hs.y);
    atomicAdd(&hsum[c4*4 + 2], hs.z);
    atomicAdd(&hsum[c4*4 + 3], hs.w);
    __syncthreads();
    if (tid < 32) atomicAdd(&g_asum[b*256 + g*32 + tid], hsum[tid]);
}

// ---------- GEMM c (fp16): cc = x @ mlp_c_w^T ; PERMUTED cc ; cc-only sums ----------
__global__ __launch_bounds__(128) void k_mma_c3h() {
    extern __shared__ __half hsm[];
    __shared__ float scol[2][128];
    int tid = threadIdx.x, wid = tid >> 5, lane = tid & 31;
    int lr = lane >> 2, lc = lane & 3;
    int wm = wid >> 1, wn = wid & 1;
    int row0 = blockIdx.x * 128, col0 = blockIdx.y * 128;
    scol[0][tid] = 0.f; scol[1][tid] = 0.f;
    uint32_t sbase = smem_u32(hsm);

    auto stage_cp = [&](int ch, int s) {
        uint32_t sb0 = sbase + (uint32_t)(s * STGH * 2);
        int k0 = ch * 32;
        #pragma unroll
        for (int i = 0; i < 4; i++) {
            int idx = tid + i*128, r = idx >> 2, q = idx & 3;
            cp16(sb0 + (uint32_t)(r*64 + q*16),
                 &g_xh[(size_t)(row0 + r)*256 + k0 + q*8]);
        }
        #pragma unroll
        for (int i = 0; i < 4; i++) {
            int idx = tid + i*128, r = idx >> 2, q = idx & 3;
            cp16(sb0 + (uint32_t)(128*64 + r*64 + q*16),
                 &g_wmh[(size_t)(col0 + r)*256 + k0 + q*8]);
        }
        CP_COMMIT();
    };
    stage_cp(0, 0); stage_cp(1, 1); stage_cp(2, 2);

    float acc[4][8][4] = {};
    for (int ch = 0; ch < 8; ch++) {
        if (ch < 6) CP_WAIT2(); else if (ch == 6) CP_WAIT1(); else CP_WAIT0();
        __syncthreads();
        const __half* Ab = hsm + (ch % 3) * STGH;
        const __half* Bb = Ab + 128*CHH;
        uint4 Alo[4], Ahi[4], Bv[8];
        #pragma unroll
        for (int mi = 0; mi < 4; mi++) {
            Alo[mi] = *(const uint4*)&Ab[(wm*64 + mi*16 + lr)*CHH + lc*8];
            Ahi[mi] = *(const uint4*)&Ab[(wm*64 + mi*16 + 8 + lr)*CHH + lc*8];
        }
        #pragma unroll
        for (int nj = 0; nj < 8; nj++)
            Bv[nj] = *(const uint4*)&Bb[(wn*64 + nj*8 + lr)*CHH + lc*8];
        #pragma unroll
        for (int mi = 0; mi < 4; mi++) {
            #pragma unroll
            for (int nj = 0; nj < 8; nj++) {
                mma_h(acc[mi][nj], Alo[mi].x, Ahi[mi].x, Alo[mi].y, Ahi[mi].y, Bv[nj].x, Bv[nj].y);
                mma_h(acc[mi][nj], Alo[mi].z, Ahi[mi].z, Alo[mi].w, Ahi[mi].w, Bv[nj].z, Bv[nj].w);
            }
        }
        __syncthreads();
        if (ch < 5) stage_cp(ch + 3, ch % 3);
    }

    int bimg = row0 / HWp;
    int bsplit = (bimg + 1) * HWp;
    #pragma unroll
    for (int nj = 0; nj < 8; nj++) {
        int colr = wn*64 + nj*8 + lc*2;
        int col = col0 + colr;
        int p0 = P16(col), p1 = P16(col + 1);
        float s0[2] = {0.f, 0.f}, s1[2] = {0.f, 0.f};
        #pragma unroll
        for (int mi = 0; mi < 4; mi++) {
            int row = row0 + wm*64 + mi*16 + lr;
            size_t ra = (size_t)row*256, rb = (size_t)(row+8)*256;
            float c0x = acc[mi][nj][0], c0y = acc[mi][nj][1];
            float c1x = acc[mi][nj][2], c1y = acc[mi][nj][3];
            g_cc[ra + p0] = c0x;  g_cc[ra + p1] = c0y;
            g_cc[rb + p0] = c1x;  g_cc[rb + p1] = c1y;
            int r0 = (row >= bsplit) ? 1 : 0;
            int r1 = (row + 8 >= bsplit) ? 1 : 0;
            s0[r0] += c0x;  s1[r0] += c0y;
            s0[r1] += c1x;  s1[r1] += c1y;
        }
        atomicAdd(&scol[0][colr],   s0[0]);
        atomicAdd(&scol[0][colr+1], s1[0]);
        if (s0[1] != 0.f || s1[1] != 0.f) {
            atomicAdd(&scol[1][colr],   s0[1]);
            atomicAdd(&scol[1][colr+1], s1[1]);
        }
    }
    __syncthreads();
    atomicAdd(&g_asum[bimg*256 + col0 + tid], scol[0][tid]);
    float v1 = scol[1][tid];
    if (v1 != 0.f && bimg + 1 < Bc)
        atomicAdd(&g_asum[(bimg+1)*256 + col0 + tid], v1);
}

// ---------- reweight MLP + pairwise softmax; a0/a1 stored PERMUTED ----------
__global__ __launch_bounds__(256) void k_small2(const float* __restrict__ fc1w,
                                                const float* __restrict__ fc1b,
                                                const float* __restrict__ fc2w,
                                                const float* __restrict__ fc2b) {
    __shared__ float sm[256];
    __shared__ float h1[64];
    int b = blockIdx.x, tid = threadIdx.x;
    sm[tid] = g_asum[b*256 + tid] * (1.0f / (float)HWp);
    __syncthreads();
    int o = tid >> 2, qtr = tid & 3;
    {
        const float* w = &fc1w[(size_t)o*256 + qtr*64];
        const float* s = &sm[qtr*64];
        float p = 0.f;
        #pragma unroll 8
        for (int c = 0; c < 64; c++) p += s[c] * w[c];
        p += __shfl_xor_sync(0xffffffffu, p, 1);
        p += __shfl_xor_sync(0xffffffffu, p, 2);
        if (qtr == 0) {
            float a = p + fc1b[o];
            h1[o] = 0.5f * a * (1.0f + erff(a * 0.70710678118654752f));
        }
    }
    __syncthreads();
    int c = tid;
    float l0 = fc2b[2*c], l1 = fc2b[2*c+1];
    #pragma unroll 8
    for (int k = 0; k < 64; k++) {
        float hv = h1[k];
        l0 += hv * fc2w[(size_t)(2*c)*64 + k];
        l1 += hv * fc2w[(size_t)(2*c+1)*64 + k];
    }
    float m = fmaxf(l0, l1);
    float e0 = expf(l0 - m), e1 = expf(l1 - m);
    float s = 1.f / (e0 + e1);
    int pc = P16(c);
    g_a0[b*256 + pc] = e0 * s;
    g_a1[b*256 + pc] = e1 * s;
}

// ---------- final GEMM (tf32, full-width 128x256, fused y-assembly; unchanged) ----------
__global__ __launch_bounds__(256) void k_mma_out3(const float* __restrict__ bp,
                                                  float* __restrict__ out) {
    extern __shared__ float dsm[];
    __shared__ float sa0[512], sa1[512];
    int tid = threadIdx.x, wid = tid >> 5, lane = tid & 31;
    int lr = lane >> 2, lc = lane & 3;
    int wm = wid >> 2, wn = wid & 3;
    int row0 = blockIdx.x * 128;
    int bimg = row0 / HWp;
    int bimg2 = (bimg + 1 < Bc) ? bimg + 1 : bimg;
    int bsplit = (bimg + 1) * HWp;
    sa0[tid]       = g_a0[bimg*256 + tid];
    sa1[tid]       = g_a1[bimg*256 + tid];
    sa0[256 + tid] = g_a0[bimg2*256 + tid];
    sa1[256 + tid] = g_a1[bimg2*256 + tid];
    uint32_t sbase = smem_u32(dsm);

    auto cpB = [&](int ch, int s) {
        uint32_t sb0 = sbase + (uint32_t)(s * STGO * 4);
        int k0 = ch * 32;
        #pragma unroll
        for (int i = 0; i < 8; i++) {
            int idx = tid + i*256, r = idx >> 3, q = idx & 7;
            cp16(sb0 + (uint32_t)((128*ST + r*ST + q*4)*4),
                 &g_wpr[(size_t)r*256 + k0 + q*4]);
        }
        CP_COMMIT();
    };
    float4 fh[4], fc[4];
    auto ldA = [&](int ch) {
        int k0 = ch * 32;
        #pragma unroll
        for (int i = 0; i < 4; i++) {
            int idx = tid + i*256, r = idx >> 3, q = idx & 7;
            size_t base = (size_t)(row0 + r)*256 + k0 + q*4;
            fh[i] = *(const float4*)&g_hw[base];
            fc[i] = *(const float4*)&g_cc[base];
        }
    };
    auto stA = [&](int ch, int s) {
        int k0 = ch * 32;
        #pragma unroll
        for (int i = 0; i < 4; i++) {
            int idx = tid + i*256, r = idx >> 3, q = idx & 7;
            int rel = ((row0 + r) >= bsplit) ? 256 : 0;
            int ki = rel + k0 + q*4;
            float4 v;
            v.x = rtf(fh[i].x * sa0[ki+0] + fc[i].x * sa1[ki+0]);
            v.y = rtf(fh[i].y * sa0[ki+1] + fc[i].y * sa1[ki+1]);
            v.z = rtf(fh[i].z * sa0[ki+2] + fc[i].z * sa1[ki+2]);
            v.w = rtf(fh[i].w * sa0[ki+3] + fc[i].w * sa1[ki+3]);
            *(float4*)&dsm[s*STGO + r*ST + q*4] = v;
        }
    };

    cpB(0, 0);
    cpB(1, 1);
    ldA(0);
    __syncthreads();
    stA(0, 0);
    ldA(1);

    float acc[4][8][4] = {};
    for (int ch = 0; ch < 8; ch++) {
        if (ch < 7) CP_WAIT1(); else CP_WAIT0();
        __syncthreads();
        const float* Ab = dsm + (ch & 1) * STGO;
        const float* Bb = Ab + 128*ST;
        #pragma unroll
        for (int g = 0; g < 2; g++) {
            float4 Alo[4], Ahi[4], Bv[8];
            #pragma unroll
            for (int mi = 0; mi < 4; mi++) {
                Alo[mi] = *(const float4*)&Ab[(wm*64 + mi*16 + lr)*ST + g*16 + lc*4];
                Ahi[mi] = *(const float4*)&Ab[(wm*64 + mi*16 + 8 + lr)*ST + g*16 + lc*4];
            }
            #pragma unroll
            for (int nj = 0; nj < 8; nj++)
                Bv[nj] = *(const float4*)&Bb[(wn*64 + nj*8 + lr)*ST + g*16 + lc*4];
            #pragma unroll
            for (int mi = 0; mi < 4; mi++) {
                uint32_t a0[4] = { __float_as_uint(Alo[mi].x), __float_as_uint(Ahi[mi].x),
                                   __float_as_uint(Alo[mi].y), __float_as_uint(Ahi[mi].y) };
                uint32_t a1[4] = { __float_as_uint(Alo[mi].z), __float_as_uint(Ahi[mi].z),
                                   __float_as_uint(Alo[mi].w), __float_as_uint(Ahi[mi].w) };
                #pragma unroll
                for (int nj = 0; nj < 8; nj++) {
                    mma_t(acc[mi][nj], a0, __float_as_uint(Bv[nj].x), __float_as_uint(Bv[nj].y));
                    mma_t(acc[mi][nj], a1, __float_as_uint(Bv[nj].z), __float_as_uint(Bv[nj].w));
                }
            }
            if (g == 0 && ch < 7) stA(ch + 1, (ch + 1) & 1);
        }
        if (ch < 6) ldA(ch + 2);
        __syncthreads();
        if (ch < 6) cpB(ch + 2, ch & 1);
    }

    #pragma unroll
    for (int nj = 0; nj < 8; nj++) {
        int col = wn*64 + nj*8 + lc*2;
        float bb0 = __ldg(&bp[col]), bb1 = __ldg(&bp[col+1]);
        #pragma unroll
        for (int mi = 0; mi < 4; mi++) {
            int row = row0 + wm*64 + mi*16 + lr;
            *(float2*)&out[(size_t)row*256 + col] =
                make_float2(acc[mi][nj][0] + bb0, acc[mi][nj][1] + bb1);
            *(float2*)&out[(size_t)(row+8)*256 + col] =
                make_float2(acc[mi][nj][2] + bb0, acc[mi][nj][3] + bb1);
        }
    }
}

extern "C" void kernel_launch(void* const* d_in, const int* in_sizes, int n_in,
                              void* d_out, int out_size) {
    const float* x        = (const float*)d_in[0];
    const float* conv1_w  = (const float*)d_in[1];
    const float* conv1_b  = (const float*)d_in[2];
    const float* bn_gamma = (const float*)d_in[3];
    const float* bn_beta  = (const float*)d_in[4];
    const float* conv2_w  = (const float*)d_in[5];
    const float* conv2_b  = (const float*)d_in[6];
    const float* mlp_c_w  = (const float*)d_in[7];
    const float* fc1_w    = (const float*)d_in[8];
    const float* fc1_b    = (const float*)d_in[9];
    const float* fc2_w    = (const float*)d_in[10];
    const float* fc2_b    = (const float*)d_in[11];
    const float* projcnn_w= (const float*)d_in[12];
    const float* projcnn_b= (const float*)d_in[13];
    float* out = (float*)d_out;

    static cudaStream_t s2 = nullptr;
    static cudaEvent_t evF = nullptr, evJ = nullptr;
    if (s2 == nullptr) {
        cudaStreamCreateWithFlags(&s2, cudaStreamNonBlocking);
        cudaEventCreateWithFlags(&evF, cudaEventDisableTiming);
        cudaEventCreateWithFlags(&evJ, cudaEventDisableTiming);
        cudaFuncSetAttribute(k_mma_c3h,  cudaFuncAttributeMaxDynamicSharedMemorySize, DSMH);
        cudaFuncSetAttribute(k_mma_out3, cudaFuncAttributeMaxDynamicSharedMemorySize, DSMO);
        cudaFuncSetAttribute(k_mma_g1h,  cudaFuncAttributeMaxDynamicSharedMemorySize, DSG1H);
    }

    k_prep   <<<1595, 256>>>(x, mlp_c_w, projcnn_w, conv1_w);

    // fork: c (x @ mlp_c_w) depends only on prep
    cudaEventRecord(evF, 0);
    cudaStreamWaitEvent(s2, evF, 0);
    k_mma_c3h<<<dim3(Nn/128, 2), 128, DSMH, s2>>>();
    cudaEventRecord(evJ, s2);

    // main chain: g1 -> kg -> invo (with fused hw sums)
    k_mma_g1h<<<Nn/128, 128, DSG1H>>>(conv1_b);
    k_mma_kg <<<Nn/128, 256>>>(bn_gamma, bn_beta, conv2_w, conv2_b);
    k_invo6b <<<dim3(Bc*28, 8), 256>>>(x);

    // join: small2 needs both hw sums (invo) and cc sums (c3h)
    cudaStreamWaitEvent(0, evJ, 0);
    k_small2 <<<Bc, 256>>>(fc1_w, fc1_b, fc2_w, fc2_b);
    k_mma_out3<<<Nn/128, 256, DSMO>>>(projcnn_b, out);
}